// round 13
// baseline (speedup 1.0000x reference)
#include <cuda_runtime.h>
#include <cuda_bf16.h>
#include <math.h>
#include <cstdint>

// Problem constants
#define NROWS 8192
#define HALF  4096
#define DIM   2048
#define PD    256
#define NT    64

// Feature gate: tcgen05 exists only in the arch-specific sm_103a/sm_100a SASS
// pass. The portable compute_103 PTX pass gets a SIMT fallback (never run).
#if !defined(__CUDA_ARCH__) || defined(__CUDA_ARCH_FEAT_SM103_ALL) || defined(__CUDA_ARCH_FEAT_SM100_ALL)
#define HAS_TCGEN05 1
#else
#define HAS_TCGEN05 0
#endif

// Scratch (device globals; no allocation allowed)
__device__ __nv_bfloat16 g_normh[NROWS * PD];   // bf16 normalized (4 MB)
__device__ __nv_bfloat16 g_Wt[PD * DIM];        // W^T bf16 [256,2048] (1 MB)
__device__ float         g_part[2 * NROWS];     // per-col-half row sums
__device__ float         g_pos[HALF];
__device__ unsigned int  g_ctr;                 // completion ticket (self-reset)

// ---------------------------------------------------------------------------
// PTX helpers
// ---------------------------------------------------------------------------
__device__ __forceinline__ uint32_t smem_to_u32(const void* p) {
    uint32_t a;
    asm("{ .reg .u64 t; cvta.to.shared.u64 t, %1; cvt.u32.u64 %0, t; }"
        : "=r"(a) : "l"(p));
    return a;
}
__device__ __forceinline__ uint32_t elect_one_pred() {
    uint32_t pred;
    asm volatile("{\n\t.reg .pred p;\n\telect.sync _|p, 0xFFFFFFFF;\n\t"
                 "selp.b32 %0, 1, 0, p;\n\t}" : "=r"(pred));
    return pred;
}
#define TCGEN05_ALLOC(smem_addr, nCols) \
    asm volatile("tcgen05.alloc.cta_group::1.sync.aligned.shared::cta.b32 [%0], %1;" \
        :: "r"((uint32_t)(smem_addr)), "r"((uint32_t)(nCols)) : "memory")
#define TCGEN05_DEALLOC(tmem, nCols) \
    asm volatile("tcgen05.dealloc.cta_group::1.sync.aligned.b32 %0, %1;" \
        :: "r"(tmem), "r"((uint32_t)(nCols)))
#define TCGEN05_RELINQUISH() \
    asm volatile("tcgen05.relinquish_alloc_permit.cta_group::1.sync.aligned;")
#define TCGEN05_COMMIT(mbar) \
    asm volatile("tcgen05.commit.cta_group::1.mbarrier::arrive::one.shared::cluster.b64 [%0];" \
        :: "r"((uint32_t)(mbar)) : "memory")
#define TCGEN05_WAIT_LD()  asm volatile("tcgen05.wait::ld.sync.aligned;" ::: "memory")
#define TCGEN05_FENCE_BEFORE() asm volatile("tcgen05.fence::before_thread_sync;" ::: "memory")
#define TCGEN05_FENCE_AFTER()  asm volatile("tcgen05.fence::after_thread_sync;" ::: "memory")
#define FENCE_PROXY_ASYNC() asm volatile("fence.proxy.async.shared::cta;" ::: "memory")
#define MBARRIER_INIT(mbar, cnt) \
    asm volatile("mbarrier.init.shared.b64 [%0], %1;" \
        :: "r"((uint32_t)(mbar)), "r"((uint32_t)(cnt)) : "memory")
#define MBARRIER_INVAL(mbar) \
    asm volatile("mbarrier.inval.shared.b64 [%0];" :: "r"((uint32_t)(mbar)) : "memory")
#define MBARRIER_WAIT_PARITY(mbar, par) do {                                     \
    uint32_t _m = (uint32_t)(mbar), _p = (uint32_t)(par), _d;                    \
    asm volatile("{\n\t.reg .pred p;\n\t"                                        \
        "mbarrier.try_wait.parity.acquire.cta.shared::cta.b64 p, [%1], %2;\n\t"  \
        "selp.b32 %0, 1, 0, p;\n\t}" : "=r"(_d) : "r"(_m), "r"(_p) : "memory");  \
    if (!_d) {                                                                   \
        asm volatile("{\n\t.reg .pred P1;\n\tWL_%=:\n\t"                         \
            "mbarrier.try_wait.parity.acquire.cta.shared::cta.b64 P1, [%0], %1, 0x989680;\n\t" \
            "@P1 bra.uni WD_%=;\n\tbra.uni WL_%=;\n\tWD_%=:\n\t}"                \
            :: "r"(_m), "r"(_p) : "memory");                                     \
    } } while (0)
#define TCGEN05_LD_32X32B_X32(r, tmem) \
    asm volatile("tcgen05.ld.sync.aligned.32x32b.x32.b32 " \
        "{%0, %1, %2, %3, %4, %5, %6, %7, %8, %9, %10, %11, %12, %13, %14, %15, " \
        "%16, %17, %18, %19, %20, %21, %22, %23, %24, %25, %26, %27, %28, %29, %30, %31}, [%32];" \
        : "=r"((r)[0]),  "=r"((r)[1]),  "=r"((r)[2]),  "=r"((r)[3]),  \
          "=r"((r)[4]),  "=r"((r)[5]),  "=r"((r)[6]),  "=r"((r)[7]),  \
          "=r"((r)[8]),  "=r"((r)[9]),  "=r"((r)[10]), "=r"((r)[11]), \
          "=r"((r)[12]), "=r"((r)[13]), "=r"((r)[14]), "=r"((r)[15]), \
          "=r"((r)[16]), "=r"((r)[17]), "=r"((r)[18]), "=r"((r)[19]), \
          "=r"((r)[20]), "=r"((r)[21]), "=r"((r)[22]), "=r"((r)[23]), \
          "=r"((r)[24]), "=r"((r)[25]), "=r"((r)[26]), "=r"((r)[27]), \
          "=r"((r)[28]), "=r"((r)[29]), "=r"((r)[30]), "=r"((r)[31]) \
        : "r"(tmem))
#define CP_ASYNC16(smem_u32, gptr) \
    asm volatile("cp.async.cg.shared.global [%0], [%1], 16;" \
        :: "r"((uint32_t)(smem_u32)), "l"(gptr) : "memory")
#define CP_COMMIT() asm volatile("cp.async.commit_group;" ::: "memory")
#define CP_WAIT(n)  asm volatile("cp.async.wait_group %0;" :: "n"(n) : "memory")
// SW128 descriptor: layout=2, version=1(Blackwell), SBO=64, LBO=1
#define SMEM_DESC_BASE_SW128 \
    ((uint64_t(2) << 61) | (uint64_t(1) << 46) | (uint64_t(64) << 32) | (uint64_t(1) << 16))
#define MAKE_SMEM_DESC(addr) (SMEM_DESC_BASE_SW128 | ((uint64_t)((addr) >> 4) & 0x3FFF))
#define SW128(off) ((off) ^ (((off) >> 3) & 0x70))

#if HAS_TCGEN05
__device__ __forceinline__ void mma_f16_ss(uint32_t d_tmem, uint64_t a_desc,
                                           uint64_t b_desc, uint32_t idesc,
                                           bool accum) {
    uint32_t en = accum ? 1u : 0u;
    asm volatile(
        "{\n\t.reg .pred p;\n\tsetp.ne.u32 p, %5, 0;\n\t"
        "tcgen05.mma.cta_group::1.kind::f16 [%0], %1, %2, %3, {%4, %4, %4, %4}, p;\n\t}"
        :: "r"(d_tmem), "l"(a_desc), "l"(b_desc), "r"(idesc), "r"(0u), "r"(en)
        : "memory");
}
#endif

// idesc: dtype F32, atype/btype BF16, M=128; N=128 / 256
#define SIM_IDESC  ((1u << 4) | (1u << 7) | (1u << 10) | ((128u / 8u) << 17) | ((128u / 16u) << 24))
#define GEMM_IDESC ((1u << 4) | (1u << 7) | (1u << 10) | ((256u / 8u) << 17) | ((128u / 16u) << 24))

#if HAS_TCGEN05
// 16 chained K=16 MMAs, K=256, 128x256-bf16 SW128 tiles (16 atom-rows x 4 cols)
__device__ __forceinline__ void issue_tile_mma(uint32_t d_tmem, uint32_t a_smem,
                                               uint32_t b_smem, uint32_t mbar) {
    uint64_t a_base = MAKE_SMEM_DESC(a_smem);
    uint64_t b_base = MAKE_SMEM_DESC(b_smem);
    if (elect_one_pred()) {
        #pragma unroll
        for (int s = 0; s < 16; s++) {
            uint64_t off = (uint64_t)((s >> 2) * 1024 + (s & 3) * 2);
            mma_f16_ss(d_tmem, a_base + off, b_base + off, SIM_IDESC, s > 0);
        }
        TCGEN05_COMMIT(mbar);
    }
}
// 8 chained K=16 MMAs, K=128: A tile 128x128, B tile 256x128, N=256.
__device__ __forceinline__ void g1_issue(uint32_t d_tmem, uint32_t a_smem,
                                         uint32_t b_smem, uint32_t mbar,
                                         bool first_chunk) {
    uint64_t a_base = MAKE_SMEM_DESC(a_smem);
    uint64_t b_base = MAKE_SMEM_DESC(b_smem);
    if (elect_one_pred()) {
        #pragma unroll
        for (int s = 0; s < 8; s++) {
            uint64_t offA = (uint64_t)((s >> 2) * 1024 + (s & 3) * 2);
            uint64_t offB = (uint64_t)((s >> 2) * 2048 + (s & 3) * 2);
            mma_f16_ss(d_tmem, a_base + offA, b_base + offB, GEMM_IDESC,
                       !(first_chunk && s == 0));
        }
        TCGEN05_COMMIT(mbar);
    }
}
// A chunk loader: X[row0..row0+127][k0..k0+127] fp32 -> bf16 SW128 (32 KB)
__device__ __forceinline__ void g1_load_A(const float* __restrict__ X, int row0,
                                          int k0, char* smem, uint32_t A_OFF,
                                          int tid) {
    #pragma unroll
    for (int i = 0; i < 8; i++) {
        int u = tid + i * 256;
        int r = u >> 4, q = u & 15;
        const float* src = X + (size_t)(row0 + r) * DIM + k0 + q * 8;
        float4 v0 = *(const float4*)src;
        float4 v1 = *(const float4*)(src + 4);
        __nv_bfloat162 h[4];
        h[0] = __floats2bfloat162_rn(v0.x, v0.y);
        h[1] = __floats2bfloat162_rn(v0.z, v0.w);
        h[2] = __floats2bfloat162_rn(v1.x, v1.y);
        h[3] = __floats2bfloat162_rn(v1.z, v1.w);
        uint32_t byte_off = (uint32_t)((r >> 3) + ((q >> 3) << 4)) * 1024u
                          + (uint32_t)(r & 7) * 128u + (uint32_t)(q & 7) * 16u;
        *(uint4*)(smem + A_OFF + SW128(byte_off)) = *(uint4*)h;
    }
}
// B chunk loader: Wt[0..255][k0..k0+127] bf16 via cp.async (64 KB)
__device__ __forceinline__ void g1_load_B(const __nv_bfloat16* __restrict__ Wt,
                                          int k0, uint32_t smem_base,
                                          uint32_t B_OFF, int tid) {
    #pragma unroll
    for (int i = 0; i < 16; i++) {
        int u = tid + i * 256;
        int r = u >> 4, q = u & 15;
        uint32_t byte_off = (uint32_t)((r >> 3) + ((q >> 3) << 5)) * 1024u
                          + (uint32_t)(r & 7) * 128u + (uint32_t)(q & 7) * 16u;
        CP_ASYNC16(smem_base + B_OFF + SW128(byte_off),
                   Wt + (size_t)r * DIM + k0 + q * 8);
    }
}
#endif

// ---------------------------------------------------------------------------
// K0: Wt[256,2048] bf16 = transpose(W[2048,256] fp32). 64x64 tiles.
// ---------------------------------------------------------------------------
__global__ void __launch_bounds__(256) k_prep(const float* __restrict__ W,
                                              __nv_bfloat16* __restrict__ Wt)
{
    __shared__ float S[64][68];
    const int k0 = blockIdx.x * 64, n0 = blockIdx.y * 64;
    const int tid = threadIdx.x;

    #pragma unroll
    for (int i = 0; i < 4; i++) {
        int t = tid + i * 256;
        int r = t >> 4, c4 = t & 15;
        float4 v = *(const float4*)&W[(size_t)(k0 + r) * PD + n0 + c4 * 4];
        S[r][c4 * 4 + 0] = v.x; S[r][c4 * 4 + 1] = v.y;
        S[r][c4 * 4 + 2] = v.z; S[r][c4 * 4 + 3] = v.w;
    }
    __syncthreads();
    #pragma unroll
    for (int i = 0; i < 2; i++) {
        int u = tid + i * 256;
        int n = u >> 3, ku = u & 7;
        __nv_bfloat162 h[4];
        #pragma unroll
        for (int m = 0; m < 4; m++)
            h[m] = __floats2bfloat162_rn(S[ku * 8 + 2 * m][n], S[ku * 8 + 2 * m + 1][n]);
        *(uint4*)&Wt[(size_t)(n0 + n) * DIM + k0 + ku * 8] = *(uint4*)h;
    }
}

// ---------------------------------------------------------------------------
// K1: tcgen05 GEMM1 + bias + fused L2-normalize -> bf16. Double-buffered K=128.
// ---------------------------------------------------------------------------
__global__ void __launch_bounds__(256, 1) k_gemm1_tc(
    const float* __restrict__ X, const __nv_bfloat16* __restrict__ Wt,
    const float* __restrict__ b, __nv_bfloat16* __restrict__ Nh)
{
    extern __shared__ __align__(16) char smem[];
    __shared__ float s_red[128][2];
    __shared__ float s_bias[256];

    const int tid = threadIdx.x;
    const int row0 = blockIdx.x * 128;
    s_bias[tid] = b[tid];

#if HAS_TCGEN05
    const uint32_t smem_base = smem_to_u32(smem);
    const uint32_t aoff = ((smem_base + 1024 + 1023) & ~1023u) - smem_base;
    const uint32_t A_OFF0 = aoff;
    const uint32_t A_OFF1 = aoff + 32768;
    const uint32_t B_OFF0 = aoff + 65536;
    const uint32_t B_OFF1 = aoff + 131072;
    const uint32_t TPTR = 0, MB0 = 16, MB1 = 24;

    if (tid < 32) {
        TCGEN05_ALLOC(smem_base + TPTR, 256);
        TCGEN05_RELINQUISH();
    }
    if (tid == 0) { MBARRIER_INIT(smem_base + MB0, 1); MBARRIER_INIT(smem_base + MB1, 1); }
    __syncthreads();
    uint32_t tmem;
    asm volatile("ld.shared.b32 %0, [%1];" : "=r"(tmem) : "r"(smem_base + TPTR));

    g1_load_B(Wt, 0, smem_base, B_OFF0, tid);
    CP_COMMIT();
    g1_load_A(X, row0, 0, smem, A_OFF0, tid);
    CP_WAIT(0);
    __syncthreads();
    FENCE_PROXY_ASYNC();

    int ph0 = 0, ph1 = 0;
    for (int c = 0; c < 16; c++) {
        const int buf = c & 1;
        if (tid < 32)
            g1_issue(tmem, smem_base + (buf ? A_OFF1 : A_OFF0),
                     smem_base + (buf ? B_OFF1 : B_OFF0),
                     smem_base + (buf ? MB1 : MB0), c == 0);
        if (c + 1 < 16) {
            if (c >= 1) {
                if (buf) { MBARRIER_WAIT_PARITY(smem_base + MB0, ph0); ph0 ^= 1; }
                else     { MBARRIER_WAIT_PARITY(smem_base + MB1, ph1); ph1 ^= 1; }
            }
            g1_load_B(Wt, (c + 1) * 128, smem_base, buf ? B_OFF0 : B_OFF1, tid);
            CP_COMMIT();
            g1_load_A(X, row0, (c + 1) * 128, smem, buf ? A_OFF0 : A_OFF1, tid);
            CP_WAIT(0);
            __syncthreads();
            FENCE_PROXY_ASYNC();
        }
    }
    MBARRIER_WAIT_PARITY(smem_base + MB1, ph1);
    TCGEN05_FENCE_AFTER();

    const int w = tid >> 5, lane = tid & 31;
    const int row = (w & 3) * 32 + lane;
    const int half = w >> 2;
    const uint32_t tbase = tmem + half * 128;

    float sumsq = 0.f;
    #pragma unroll
    for (int c4 = 0; c4 < 4; c4++) {
        uint32_t r[32];
        TCGEN05_LD_32X32B_X32(r, tbase + c4 * 32);
        TCGEN05_WAIT_LD();
        #pragma unroll
        for (int j = 0; j < 32; j++) {
            float v = __uint_as_float(r[j]) + s_bias[half * 128 + c4 * 32 + j];
            sumsq += v * v;
        }
    }
    s_red[row][half] = sumsq;
    __syncthreads();
    float inv = 1.0f / fmaxf(sqrtf(s_red[row][0] + s_red[row][1]), 1e-12f);

    const size_t gbase = (size_t)(row0 + row) * PD + half * 128;
    #pragma unroll
    for (int c4 = 0; c4 < 4; c4++) {
        uint32_t r[32];
        TCGEN05_LD_32X32B_X32(r, tbase + c4 * 32);
        TCGEN05_WAIT_LD();
        float v[32];
        #pragma unroll
        for (int j = 0; j < 32; j++)
            v[j] = (__uint_as_float(r[j]) + s_bias[half * 128 + c4 * 32 + j]) * inv;
        __nv_bfloat162 hh[16];
        #pragma unroll
        for (int j2 = 0; j2 < 16; j2++)
            hh[j2] = __floats2bfloat162_rn(v[2 * j2], v[2 * j2 + 1]);
        #pragma unroll
        for (int q = 0; q < 4; q++)
            *(uint4*)&Nh[gbase + c4 * 32 + q * 8] = ((uint4*)hh)[q];
    }
    TCGEN05_FENCE_BEFORE();

    __syncthreads();
    if (tid == 0) { MBARRIER_INVAL(smem_base + MB0); MBARRIER_INVAL(smem_base + MB1); }
    __syncthreads();
    if (tid < 32) TCGEN05_DEALLOC(tmem, 256);
#else
    const int row = row0 + (tid & 127);
    if (tid < 128) {
        float sumsq = 0.f;
        for (int n = 0; n < PD; n++) {
            float s = 0.f;
            for (int k = 0; k < DIM; k++)
                s += X[(size_t)row * DIM + k] * __bfloat162float(Wt[(size_t)n * DIM + k]);
            s += s_bias[n];
            sumsq += s * s;
        }
        float inv = 1.0f / fmaxf(sqrtf(sumsq), 1e-12f);
        for (int n = 0; n < PD; n++) {
            float s = 0.f;
            for (int k = 0; k < DIM; k++)
                s += X[(size_t)row * DIM + k] * __bfloat162float(Wt[(size_t)n * DIM + k]);
            Nh[(size_t)row * PD + n] = __float2bfloat16((s + s_bias[n]) * inv);
        }
    }
#endif
}

// ---------------------------------------------------------------------------
// Fused loss tail: called by the LAST-arriving sim CTA. 256 threads reduce
// 8192 log(neg) + 4096 pos in fixed order and write the scalar loss.
// ---------------------------------------------------------------------------
__device__ __forceinline__ void loss_reduce(const float* __restrict__ part,
                                            const float* __restrict__ pos,
                                            float* __restrict__ out,
                                            float* sh, int tid)
{
    float s = 0.f;
    #pragma unroll
    for (int i = 0; i < 32; i++) {
        int idx = tid + i * 256;
        s += logf(part[idx] + part[NROWS + idx]);
    }
    float p = 0.f;
    #pragma unroll
    for (int i = 0; i < 16; i++)
        p += pos[tid + i * 256];

    sh[tid] = s;
    __syncthreads();
    #pragma unroll
    for (int o = 128; o > 0; o >>= 1) {
        if (tid < o) sh[tid] += sh[tid + o];
        __syncthreads();
    }
    float L = sh[0];
    __syncthreads();
    sh[tid] = p;
    __syncthreads();
    #pragma unroll
    for (int o = 128; o > 0; o >>= 1) {
        if (tid < o) sh[tid] += sh[tid + o];
        __syncthreads();
    }
    if (tid == 0)
        out[0] = (L - 20.0f * sh[0]) / (float)NROWS;
}

// ---------------------------------------------------------------------------
// K4: A-resident pipelined sim+exp+rowsum, compare-free fast path, FUSED LOSS.
// Grid (64 bi, 2 bhalf), 256 thr. Special tile per CTA:
//  - diag CTA (bhalf == bi>>5): tile t=bi&31 masks the diagonal exp.
//  - pos CTA (bhalf==1, bi<32): tile t=bi captures raw sim[gi][gi+4096] -> pos.
// Last-arriving CTA (atomic ticket over 128) computes the final loss.
// ---------------------------------------------------------------------------
__global__ void __launch_bounds__(256, 1) k_sim_rows(
    const __nv_bfloat16* __restrict__ Nh, float* __restrict__ part,
    float* __restrict__ pos, unsigned int* __restrict__ ctr,
    float* __restrict__ out)
{
    extern __shared__ __align__(16) char smem[];
    __shared__ float s_red[128][2];
    __shared__ float s_lred[256];
    __shared__ bool s_last;
    const int tid = threadIdx.x;
    const int bi = blockIdx.x, bhalf = blockIdx.y;
    const int ro = bi * 128;

#if HAS_TCGEN05
    const uint32_t smem_base = smem_to_u32(smem);
    const uint32_t aoff = ((smem_base + 1024 + 1023) & ~1023u) - smem_base;
    const uint32_t A_OFF = aoff;
    const uint32_t B_OFF0 = aoff + 65536;
    const uint32_t B_OFF1 = aoff + 131072;
    const uint32_t TPTR = 0, MBAR0 = 16, MBAR1 = 24;

    if (tid < 32) {
        TCGEN05_ALLOC(smem_base + TPTR, 256);
        TCGEN05_RELINQUISH();
    }
    if (tid == 0) { MBARRIER_INIT(smem_base + MBAR0, 1); MBARRIER_INIT(smem_base + MBAR1, 1); }
    __syncthreads();
    uint32_t tmem;
    asm volatile("ld.shared.b32 %0, [%1];" : "=r"(tmem) : "r"(smem_base + TPTR));
    const uint32_t D0 = tmem, D1 = tmem + 128;

    const __nv_bfloat16* Arows = Nh + (size_t)ro * PD;
    const __nv_bfloat16* Bbase = Nh + (size_t)(bhalf * HALF) * PD;

    // Hoisted addressing: absolute smem dsts for both B buffers + gmem offsets.
    uint32_t dstA[16], dst0[16], dst1[16], goff[16];
    #pragma unroll
    for (int it = 0; it < 16; it++) {
        int idx = tid + it * 256;
        int r = idx >> 5, q = idx & 31;
        uint32_t byte_off = (uint32_t)((r >> 3) + ((q >> 3) << 4)) * 1024u
                          + (uint32_t)(r & 7) * 128u + (uint32_t)(q & 7) * 16u;
        uint32_t sw = SW128(byte_off);
        dstA[it] = smem_base + A_OFF + sw;
        dst0[it] = smem_base + B_OFF0 + sw;
        dst1[it] = smem_base + B_OFF1 + sw;
        goff[it] = (uint32_t)(r * PD + q * 8);
    }

    // Prologue
    #pragma unroll
    for (int it = 0; it < 16; it++) {
        CP_ASYNC16(dstA[it], Arows + goff[it]);
        CP_ASYNC16(dst0[it], Bbase + goff[it]);
    }
    CP_COMMIT();
    #pragma unroll
    for (int it = 0; it < 16; it++)
        CP_ASYNC16(dst1[it], Bbase + 128 * PD + goff[it]);
    CP_COMMIT();
    CP_WAIT(1);
    __syncthreads();
    FENCE_PROXY_ASYNC();

    if (tid < 32) issue_tile_mma(D0, smem_base + A_OFF, smem_base + B_OFF0,
                                 smem_base + MBAR0);

    // Epilogue mapping: warp w -> rows (w&3)*32+lane, col half w>>2 (64 cols)
    const int w = tid >> 5, lane = tid & 31;
    const int row = (w & 3) * 32 + lane;
    const int chalf = w >> 2;
    const int gi = ro + row;

    // Special tile per CTA
    const bool sp_diag = (bhalf == (bi >> 5));
    const int t_sp = sp_diag ? (bi & 31) : ((bhalf == 1 && bi < 32) ? bi : -1);
    const int sp_col = sp_diag ? gi : gi + HALF;

    int ph0 = 0, ph1 = 0;
    float acc0 = 0.f, acc1 = 0.f, acc2 = 0.f, acc3 = 0.f;
    float posval = 0.f;

    for (int t = 0; t < 32; t++) {
        const int buf = t & 1;
        const uint32_t mb = smem_base + (buf ? MBAR1 : MBAR0);

        if (buf) { MBARRIER_WAIT_PARITY(mb, ph1); ph1 ^= 1; }
        else     { MBARRIER_WAIT_PARITY(mb, ph0); ph0 ^= 1; }

        if (t + 2 < 32) {
            const __nv_bfloat16* Brows = Bbase + (size_t)(t + 2) * 128 * PD;
            #pragma unroll
            for (int it = 0; it < 16; it++)
                CP_ASYNC16(buf ? dst1[it] : dst0[it], Brows + goff[it]);
        }
        CP_COMMIT();
        CP_WAIT(1);
        __syncthreads();
        FENCE_PROXY_ASYNC();
        TCGEN05_FENCE_AFTER();

        if (t + 1 < 32 && tid < 32)
            issue_tile_mma(buf ? D0 : D1, smem_base + A_OFF,
                           smem_base + (buf ? B_OFF0 : B_OFF1),
                           smem_base + (buf ? MBAR0 : MBAR1));

        const uint32_t dt = (buf ? D1 : D0) + chalf * 64;
        if (t != t_sp) {
            // fast path: no compares, 4 accumulators
            #pragma unroll
            for (int c4 = 0; c4 < 2; c4++) {
                uint32_t r[32];
                TCGEN05_LD_32X32B_X32(r, dt + c4 * 32);
                TCGEN05_WAIT_LD();
                #pragma unroll
                for (int j = 0; j < 32; j += 4) {
                    acc0 += __expf(10.0f * __uint_as_float(r[j]));
                    acc1 += __expf(10.0f * __uint_as_float(r[j + 1]));
                    acc2 += __expf(10.0f * __uint_as_float(r[j + 2]));
                    acc3 += __expf(10.0f * __uint_as_float(r[j + 3]));
                }
            }
        } else if (sp_diag) {
            const int jb = bhalf * HALF + t * 128 + chalf * 64;
            #pragma unroll
            for (int c4 = 0; c4 < 2; c4++) {
                uint32_t r[32];
                TCGEN05_LD_32X32B_X32(r, dt + c4 * 32);
                TCGEN05_WAIT_LD();
                #pragma unroll
                for (int j = 0; j < 32; j++) {
                    float e = __expf(10.0f * __uint_as_float(r[j]));
                    acc0 += (sp_col == jb + c4 * 32 + j) ? 0.0f : e;
                }
            }
        } else {
            const int jb = bhalf * HALF + t * 128 + chalf * 64;
            #pragma unroll
            for (int c4 = 0; c4 < 2; c4++) {
                uint32_t r[32];
                TCGEN05_LD_32X32B_X32(r, dt + c4 * 32);
                TCGEN05_WAIT_LD();
                #pragma unroll
                for (int j = 0; j < 32; j++) {
                    float v = __uint_as_float(r[j]);
                    acc0 += __expf(10.0f * v);
                    if (sp_col == jb + c4 * 32 + j) posval = v;
                }
            }
        }
        TCGEN05_FENCE_BEFORE();
    }

    if (t_sp >= 0 && !sp_diag && (row >> 6) == chalf)
        pos[gi] = posval;

    s_red[row][chalf] = (acc0 + acc1) + (acc2 + acc3);
    __syncthreads();
    if (tid < 128)
        part[(size_t)bhalf * NROWS + ro + tid] = s_red[tid][0] + s_red[tid][1];

    // cleanup (overlaps with other CTAs still running)
    if (tid == 0) { MBARRIER_INVAL(smem_base + MBAR0); MBARRIER_INVAL(smem_base + MBAR1); }
    __syncthreads();
    if (tid < 32) TCGEN05_DEALLOC(tmem, 256);

    // --- Fused loss: last-arriving CTA reduces everything ---
    __threadfence();
    __syncthreads();
    if (tid == 0) {
        unsigned int old = atomicAdd(ctr, 1u);
        s_last = (old == 127u);
    }
    __syncthreads();
    if (s_last) {
        __threadfence();   // acquire: make all CTAs' part/pos writes visible
        loss_reduce(part, pos, out, s_lred, tid);
        if (tid == 0) *ctr = 0u;   // reset for next graph replay
    }
#else
    // SIMT fallback (compile-only for the portable PTX pass)
    if (tid < 128) {
        const int gi = ro + tid;
        const __nv_bfloat16* arow = Nh + (size_t)gi * PD;
        float rowsum = 0.f;
        for (int j = 0; j < HALF; j++) {
            int gj = bhalf * HALF + j;
            const __nv_bfloat16* brow = Nh + (size_t)gj * PD;
            float s = 0.f;
            for (int k = 0; k < PD; k++)
                s += __bfloat162float(arow[k]) * __bfloat162float(brow[k]);
            rowsum += (gi == gj) ? 0.0f : __expf(10.0f * s);
        }
        part[(size_t)bhalf * NROWS + gi] = rowsum;
        if (bhalf == 1 && bi < 32) {
            const __nv_bfloat16* brow = Nh + (size_t)(gi + HALF) * PD;
            float s = 0.f;
            for (int k = 0; k < PD; k++)
                s += __bfloat162float(arow[k]) * __bfloat162float(brow[k]);
            pos[gi] = s;
        }
    }
    __threadfence();
    __syncthreads();
    if (tid == 0) {
        unsigned int old = atomicAdd(ctr, 1u);
        s_last = (old == 127u);
    }
    __syncthreads();
    if (s_last) {
        __threadfence();
        loss_reduce(part, pos, out, s_lred, tid);
        if (tid == 0) *ctr = 0u;
    }
#endif
}

// ---------------------------------------------------------------------------
extern "C" void kernel_launch(void* const* d_in, const int* in_sizes, int n_in,
                              void* d_out, int out_size)
{
    const float* X = (const float*)d_in[0];  // [8192, 2048]
    const float* W = (const float*)d_in[1];  // [2048, 256]
    const float* b = (const float*)d_in[2];  // [256]
    float* out = (float*)d_out;

    __nv_bfloat16* nrh;  cudaGetSymbolAddress((void**)&nrh,  g_normh);
    __nv_bfloat16* wt;   cudaGetSymbolAddress((void**)&wt,   g_Wt);
    float* part;         cudaGetSymbolAddress((void**)&part, g_part);
    float* pos;          cudaGetSymbolAddress((void**)&pos,  g_pos);
    unsigned int* ctr;   cudaGetSymbolAddress((void**)&ctr,  g_ctr);

    const int SIM_SMEM  = 2048 + 3 * 65536;             // 198656 B
    const int GEMM_SMEM = 2048 + 2 * 32768 + 2 * 65536; // 198656 B
    cudaFuncSetAttribute(k_sim_rows,
                         cudaFuncAttributeMaxDynamicSharedMemorySize, SIM_SMEM);
    cudaFuncSetAttribute(k_gemm1_tc,
                         cudaFuncAttributeMaxDynamicSharedMemorySize, GEMM_SMEM);

    k_prep<<<dim3(32, 4), 256>>>(W, wt);
    k_gemm1_tc<<<64, 256, GEMM_SMEM>>>(X, wt, b, nrh);
    k_sim_rows<<<dim3(64, 2), 256, SIM_SMEM>>>(nrh, part, pos, ctr, out);
}

// round 14
// speedup vs baseline: 1.0547x; 1.0547x over previous
#include <cuda_runtime.h>
#include <cuda_bf16.h>
#include <math.h>
#include <cstdint>

// Problem constants
#define NROWS 8192
#define HALF  4096
#define DIM   2048
#define PD    256
#define NT    64
#define L2E10 14.4269504088896340736f   // 10 / ln(2): exp(10x) = exp2(L2E10*x)

// Feature gate: tcgen05 exists only in the arch-specific sm_103a/sm_100a SASS
// pass. The portable compute_103 PTX pass gets a SIMT fallback (never run).
#if !defined(__CUDA_ARCH__) || defined(__CUDA_ARCH_FEAT_SM103_ALL) || defined(__CUDA_ARCH_FEAT_SM100_ALL)
#define HAS_TCGEN05 1
#else
#define HAS_TCGEN05 0
#endif

// Scratch (device globals; no allocation allowed)
__device__ __nv_bfloat16 g_normh[NROWS * PD];   // bf16 normalized (4 MB)
__device__ __nv_bfloat16 g_Wt[PD * DIM];        // W^T bf16 [256,2048] (1 MB)
__device__ float         g_part[2 * NROWS];     // per-col-half row sums
__device__ float         g_pos[HALF];
__device__ float         g_lred[64];            // per-block log partials
__device__ float         g_ppart[64];           // per-block pos partials
__device__ unsigned int  g_ctr;                 // completion ticket (self-reset)

// ---------------------------------------------------------------------------
// PTX helpers
// ---------------------------------------------------------------------------
__device__ __forceinline__ uint32_t smem_to_u32(const void* p) {
    uint32_t a;
    asm("{ .reg .u64 t; cvta.to.shared.u64 t, %1; cvt.u32.u64 %0, t; }"
        : "=r"(a) : "l"(p));
    return a;
}
__device__ __forceinline__ uint32_t elect_one_pred() {
    uint32_t pred;
    asm volatile("{\n\t.reg .pred p;\n\telect.sync _|p, 0xFFFFFFFF;\n\t"
                 "selp.b32 %0, 1, 0, p;\n\t}" : "=r"(pred));
    return pred;
}
#define TCGEN05_ALLOC(smem_addr, nCols) \
    asm volatile("tcgen05.alloc.cta_group::1.sync.aligned.shared::cta.b32 [%0], %1;" \
        :: "r"((uint32_t)(smem_addr)), "r"((uint32_t)(nCols)) : "memory")
#define TCGEN05_DEALLOC(tmem, nCols) \
    asm volatile("tcgen05.dealloc.cta_group::1.sync.aligned.b32 %0, %1;" \
        :: "r"(tmem), "r"((uint32_t)(nCols)))
#define TCGEN05_RELINQUISH() \
    asm volatile("tcgen05.relinquish_alloc_permit.cta_group::1.sync.aligned;")
#define TCGEN05_COMMIT(mbar) \
    asm volatile("tcgen05.commit.cta_group::1.mbarrier::arrive::one.shared::cluster.b64 [%0];" \
        :: "r"((uint32_t)(mbar)) : "memory")
#define TCGEN05_WAIT_LD()  asm volatile("tcgen05.wait::ld.sync.aligned;" ::: "memory")
#define TCGEN05_FENCE_BEFORE() asm volatile("tcgen05.fence::before_thread_sync;" ::: "memory")
#define TCGEN05_FENCE_AFTER()  asm volatile("tcgen05.fence::after_thread_sync;" ::: "memory")
#define FENCE_PROXY_ASYNC() asm volatile("fence.proxy.async.shared::cta;" ::: "memory")
#define MBARRIER_INIT(mbar, cnt) \
    asm volatile("mbarrier.init.shared.b64 [%0], %1;" \
        :: "r"((uint32_t)(mbar)), "r"((uint32_t)(cnt)) : "memory")
#define MBARRIER_INVAL(mbar) \
    asm volatile("mbarrier.inval.shared.b64 [%0];" :: "r"((uint32_t)(mbar)) : "memory")
#define MBARRIER_WAIT_PARITY(mbar, par) do {                                     \
    uint32_t _m = (uint32_t)(mbar), _p = (uint32_t)(par), _d;                    \
    asm volatile("{\n\t.reg .pred p;\n\t"                                        \
        "mbarrier.try_wait.parity.acquire.cta.shared::cta.b64 p, [%1], %2;\n\t"  \
        "selp.b32 %0, 1, 0, p;\n\t}" : "=r"(_d) : "r"(_m), "r"(_p) : "memory");  \
    if (!_d) {                                                                   \
        asm volatile("{\n\t.reg .pred P1;\n\tWL_%=:\n\t"                         \
            "mbarrier.try_wait.parity.acquire.cta.shared::cta.b64 P1, [%0], %1, 0x989680;\n\t" \
            "@P1 bra.uni WD_%=;\n\tbra.uni WL_%=;\n\tWD_%=:\n\t}"                \
            :: "r"(_m), "r"(_p) : "memory");                                     \
    } } while (0)
#define TCGEN05_LD_32X32B_X32(r, tmem) \
    asm volatile("tcgen05.ld.sync.aligned.32x32b.x32.b32 " \
        "{%0, %1, %2, %3, %4, %5, %6, %7, %8, %9, %10, %11, %12, %13, %14, %15, " \
        "%16, %17, %18, %19, %20, %21, %22, %23, %24, %25, %26, %27, %28, %29, %30, %31}, [%32];" \
        : "=r"((r)[0]),  "=r"((r)[1]),  "=r"((r)[2]),  "=r"((r)[3]),  \
          "=r"((r)[4]),  "=r"((r)[5]),  "=r"((r)[6]),  "=r"((r)[7]),  \
          "=r"((r)[8]),  "=r"((r)[9]),  "=r"((r)[10]), "=r"((r)[11]), \
          "=r"((r)[12]), "=r"((r)[13]), "=r"((r)[14]), "=r"((r)[15]), \
          "=r"((r)[16]), "=r"((r)[17]), "=r"((r)[18]), "=r"((r)[19]), \
          "=r"((r)[20]), "=r"((r)[21]), "=r"((r)[22]), "=r"((r)[23]), \
          "=r"((r)[24]), "=r"((r)[25]), "=r"((r)[26]), "=r"((r)[27]), \
          "=r"((r)[28]), "=r"((r)[29]), "=r"((r)[30]), "=r"((r)[31]) \
        : "r"(tmem))
#define CP_ASYNC16(smem_u32, gptr) \
    asm volatile("cp.async.cg.shared.global [%0], [%1], 16;" \
        :: "r"((uint32_t)(smem_u32)), "l"(gptr) : "memory")
#define CP_COMMIT() asm volatile("cp.async.commit_group;" ::: "memory")
#define CP_WAIT(n)  asm volatile("cp.async.wait_group %0;" :: "n"(n) : "memory")
// SW128 descriptor: layout=2, version=1(Blackwell), SBO=64, LBO=1
#define SMEM_DESC_BASE_SW128 \
    ((uint64_t(2) << 61) | (uint64_t(1) << 46) | (uint64_t(64) << 32) | (uint64_t(1) << 16))
#define MAKE_SMEM_DESC(addr) (SMEM_DESC_BASE_SW128 | ((uint64_t)((addr) >> 4) & 0x3FFF))
#define SW128(off) ((off) ^ (((off) >> 3) & 0x70))

#if HAS_TCGEN05
__device__ __forceinline__ void mma_f16_ss(uint32_t d_tmem, uint64_t a_desc,
                                           uint64_t b_desc, uint32_t idesc,
                                           bool accum) {
    uint32_t en = accum ? 1u : 0u;
    asm volatile(
        "{\n\t.reg .pred p;\n\tsetp.ne.u32 p, %5, 0;\n\t"
        "tcgen05.mma.cta_group::1.kind::f16 [%0], %1, %2, %3, {%4, %4, %4, %4}, p;\n\t}"
        :: "r"(d_tmem), "l"(a_desc), "l"(b_desc), "r"(idesc), "r"(0u), "r"(en)
        : "memory");
}
#endif

// idesc: dtype F32, atype/btype BF16, M=128; N=128 / 256
#define SIM_IDESC  ((1u << 4) | (1u << 7) | (1u << 10) | ((128u / 8u) << 17) | ((128u / 16u) << 24))
#define GEMM_IDESC ((1u << 4) | (1u << 7) | (1u << 10) | ((256u / 8u) << 17) | ((128u / 16u) << 24))

#if HAS_TCGEN05
// 16 chained K=16 MMAs, K=256, 128x256-bf16 SW128 tiles (16 atom-rows x 4 cols)
__device__ __forceinline__ void issue_tile_mma(uint32_t d_tmem, uint32_t a_smem,
                                               uint32_t b_smem, uint32_t mbar) {
    uint64_t a_base = MAKE_SMEM_DESC(a_smem);
    uint64_t b_base = MAKE_SMEM_DESC(b_smem);
    if (elect_one_pred()) {
        #pragma unroll
        for (int s = 0; s < 16; s++) {
            uint64_t off = (uint64_t)((s >> 2) * 1024 + (s & 3) * 2);
            mma_f16_ss(d_tmem, a_base + off, b_base + off, SIM_IDESC, s > 0);
        }
        TCGEN05_COMMIT(mbar);
    }
}
// 8 chained K=16 MMAs, K=128: A tile 128x128, B tile 256x128, N=256.
__device__ __forceinline__ void g1_issue(uint32_t d_tmem, uint32_t a_smem,
                                         uint32_t b_smem, uint32_t mbar,
                                         bool first_chunk) {
    uint64_t a_base = MAKE_SMEM_DESC(a_smem);
    uint64_t b_base = MAKE_SMEM_DESC(b_smem);
    if (elect_one_pred()) {
        #pragma unroll
        for (int s = 0; s < 8; s++) {
            uint64_t offA = (uint64_t)((s >> 2) * 1024 + (s & 3) * 2);
            uint64_t offB = (uint64_t)((s >> 2) * 2048 + (s & 3) * 2);
            mma_f16_ss(d_tmem, a_base + offA, b_base + offB, GEMM_IDESC,
                       !(first_chunk && s == 0));
        }
        TCGEN05_COMMIT(mbar);
    }
}
// A chunk loader: X[row0..row0+127][k0..k0+127] fp32 -> bf16 SW128 (32 KB)
__device__ __forceinline__ void g1_load_A(const float* __restrict__ X, int row0,
                                          int k0, char* smem, uint32_t A_OFF,
                                          int tid) {
    #pragma unroll
    for (int i = 0; i < 8; i++) {
        int u = tid + i * 256;
        int r = u >> 4, q = u & 15;
        const float* src = X + (size_t)(row0 + r) * DIM + k0 + q * 8;
        float4 v0 = *(const float4*)src;
        float4 v1 = *(const float4*)(src + 4);
        __nv_bfloat162 h[4];
        h[0] = __floats2bfloat162_rn(v0.x, v0.y);
        h[1] = __floats2bfloat162_rn(v0.z, v0.w);
        h[2] = __floats2bfloat162_rn(v1.x, v1.y);
        h[3] = __floats2bfloat162_rn(v1.z, v1.w);
        uint32_t byte_off = (uint32_t)((r >> 3) + ((q >> 3) << 4)) * 1024u
                          + (uint32_t)(r & 7) * 128u + (uint32_t)(q & 7) * 16u;
        *(uint4*)(smem + A_OFF + SW128(byte_off)) = *(uint4*)h;
    }
}
// B chunk loader: Wt[0..255][k0..k0+127] bf16 via cp.async (64 KB)
__device__ __forceinline__ void g1_load_B(const __nv_bfloat16* __restrict__ Wt,
                                          int k0, uint32_t smem_base,
                                          uint32_t B_OFF, int tid) {
    #pragma unroll
    for (int i = 0; i < 16; i++) {
        int u = tid + i * 256;
        int r = u >> 4, q = u & 15;
        uint32_t byte_off = (uint32_t)((r >> 3) + ((q >> 3) << 5)) * 1024u
                          + (uint32_t)(r & 7) * 128u + (uint32_t)(q & 7) * 16u;
        CP_ASYNC16(smem_base + B_OFF + SW128(byte_off),
                   Wt + (size_t)r * DIM + k0 + q * 8);
    }
}
#endif

// ---------------------------------------------------------------------------
// K0: Wt[256,2048] bf16 = transpose(W[2048,256] fp32). 64x64 tiles.
// ---------------------------------------------------------------------------
__global__ void __launch_bounds__(256) k_prep(const float* __restrict__ W,
                                              __nv_bfloat16* __restrict__ Wt)
{
    __shared__ float S[64][68];
    const int k0 = blockIdx.x * 64, n0 = blockIdx.y * 64;
    const int tid = threadIdx.x;

    #pragma unroll
    for (int i = 0; i < 4; i++) {
        int t = tid + i * 256;
        int r = t >> 4, c4 = t & 15;
        float4 v = *(const float4*)&W[(size_t)(k0 + r) * PD + n0 + c4 * 4];
        S[r][c4 * 4 + 0] = v.x; S[r][c4 * 4 + 1] = v.y;
        S[r][c4 * 4 + 2] = v.z; S[r][c4 * 4 + 3] = v.w;
    }
    __syncthreads();
    #pragma unroll
    for (int i = 0; i < 2; i++) {
        int u = tid + i * 256;
        int n = u >> 3, ku = u & 7;
        __nv_bfloat162 h[4];
        #pragma unroll
        for (int m = 0; m < 4; m++)
            h[m] = __floats2bfloat162_rn(S[ku * 8 + 2 * m][n], S[ku * 8 + 2 * m + 1][n]);
        *(uint4*)&Wt[(size_t)(n0 + n) * DIM + k0 + ku * 8] = *(uint4*)h;
    }
}

// ---------------------------------------------------------------------------
// K1: tcgen05 GEMM1 + bias + fused L2-normalize -> bf16. Double-buffered K=128.
// ---------------------------------------------------------------------------
__global__ void __launch_bounds__(256, 1) k_gemm1_tc(
    const float* __restrict__ X, const __nv_bfloat16* __restrict__ Wt,
    const float* __restrict__ b, __nv_bfloat16* __restrict__ Nh)
{
    extern __shared__ __align__(16) char smem[];
    __shared__ float s_red[128][2];
    __shared__ float s_bias[256];

    const int tid = threadIdx.x;
    const int row0 = blockIdx.x * 128;
    s_bias[tid] = b[tid];

#if HAS_TCGEN05
    const uint32_t smem_base = smem_to_u32(smem);
    const uint32_t aoff = ((smem_base + 1024 + 1023) & ~1023u) - smem_base;
    const uint32_t A_OFF0 = aoff;
    const uint32_t A_OFF1 = aoff + 32768;
    const uint32_t B_OFF0 = aoff + 65536;
    const uint32_t B_OFF1 = aoff + 131072;
    const uint32_t TPTR = 0, MB0 = 16, MB1 = 24;

    if (tid < 32) {
        TCGEN05_ALLOC(smem_base + TPTR, 256);
        TCGEN05_RELINQUISH();
    }
    if (tid == 0) { MBARRIER_INIT(smem_base + MB0, 1); MBARRIER_INIT(smem_base + MB1, 1); }
    __syncthreads();
    uint32_t tmem;
    asm volatile("ld.shared.b32 %0, [%1];" : "=r"(tmem) : "r"(smem_base + TPTR));

    g1_load_B(Wt, 0, smem_base, B_OFF0, tid);
    CP_COMMIT();
    g1_load_A(X, row0, 0, smem, A_OFF0, tid);
    CP_WAIT(0);
    __syncthreads();
    FENCE_PROXY_ASYNC();

    int ph0 = 0, ph1 = 0;
    for (int c = 0; c < 16; c++) {
        const int buf = c & 1;
        if (tid < 32)
            g1_issue(tmem, smem_base + (buf ? A_OFF1 : A_OFF0),
                     smem_base + (buf ? B_OFF1 : B_OFF0),
                     smem_base + (buf ? MB1 : MB0), c == 0);
        if (c + 1 < 16) {
            if (c >= 1) {
                if (buf) { MBARRIER_WAIT_PARITY(smem_base + MB0, ph0); ph0 ^= 1; }
                else     { MBARRIER_WAIT_PARITY(smem_base + MB1, ph1); ph1 ^= 1; }
            }
            g1_load_B(Wt, (c + 1) * 128, smem_base, buf ? B_OFF0 : B_OFF1, tid);
            CP_COMMIT();
            g1_load_A(X, row0, (c + 1) * 128, smem, buf ? A_OFF0 : A_OFF1, tid);
            CP_WAIT(0);
            __syncthreads();
            FENCE_PROXY_ASYNC();
        }
    }
    MBARRIER_WAIT_PARITY(smem_base + MB1, ph1);
    TCGEN05_FENCE_AFTER();

    const int w = tid >> 5, lane = tid & 31;
    const int row = (w & 3) * 32 + lane;
    const int half = w >> 2;
    const uint32_t tbase = tmem + half * 128;

    // Pass 1: sumsq — paired LDTM, single wait per pair
    float sumsq = 0.f;
    #pragma unroll
    for (int c8 = 0; c8 < 2; c8++) {
        uint32_t r0[32], r1[32];
        TCGEN05_LD_32X32B_X32(r0, tbase + c8 * 64);
        TCGEN05_LD_32X32B_X32(r1, tbase + c8 * 64 + 32);
        TCGEN05_WAIT_LD();
        #pragma unroll
        for (int j = 0; j < 32; j++) {
            float v0 = __uint_as_float(r0[j]) + s_bias[half * 128 + c8 * 64 + j];
            float v1 = __uint_as_float(r1[j]) + s_bias[half * 128 + c8 * 64 + 32 + j];
            sumsq += v0 * v0 + v1 * v1;
        }
    }
    s_red[row][half] = sumsq;
    __syncthreads();
    float inv = 1.0f / fmaxf(sqrtf(s_red[row][0] + s_red[row][1]), 1e-12f);

    const size_t gbase = (size_t)(row0 + row) * PD + half * 128;
    #pragma unroll
    for (int c8 = 0; c8 < 2; c8++) {
        uint32_t r0[32], r1[32];
        TCGEN05_LD_32X32B_X32(r0, tbase + c8 * 64);
        TCGEN05_LD_32X32B_X32(r1, tbase + c8 * 64 + 32);
        TCGEN05_WAIT_LD();
        float v[64];
        #pragma unroll
        for (int j = 0; j < 32; j++) {
            v[j]      = (__uint_as_float(r0[j]) + s_bias[half * 128 + c8 * 64 + j]) * inv;
            v[32 + j] = (__uint_as_float(r1[j]) + s_bias[half * 128 + c8 * 64 + 32 + j]) * inv;
        }
        __nv_bfloat162 hh[32];
        #pragma unroll
        for (int j2 = 0; j2 < 32; j2++)
            hh[j2] = __floats2bfloat162_rn(v[2 * j2], v[2 * j2 + 1]);
        #pragma unroll
        for (int q = 0; q < 8; q++)
            *(uint4*)&Nh[gbase + c8 * 64 + q * 8] = ((uint4*)hh)[q];
    }
    TCGEN05_FENCE_BEFORE();

    __syncthreads();
    if (tid == 0) { MBARRIER_INVAL(smem_base + MB0); MBARRIER_INVAL(smem_base + MB1); }
    __syncthreads();
    if (tid < 32) TCGEN05_DEALLOC(tmem, 256);
#else
    const int row = row0 + (tid & 127);
    if (tid < 128) {
        float sumsq = 0.f;
        for (int n = 0; n < PD; n++) {
            float s = 0.f;
            for (int k = 0; k < DIM; k++)
                s += X[(size_t)row * DIM + k] * __bfloat162float(Wt[(size_t)n * DIM + k]);
            s += s_bias[n];
            sumsq += s * s;
        }
        float inv = 1.0f / fmaxf(sqrtf(sumsq), 1e-12f);
        for (int n = 0; n < PD; n++) {
            float s = 0.f;
            for (int k = 0; k < DIM; k++)
                s += X[(size_t)row * DIM + k] * __bfloat162float(Wt[(size_t)n * DIM + k]);
            Nh[(size_t)row * PD + n] = __float2bfloat16((s + s_bias[n]) * inv);
        }
    }
#endif
}

// ---------------------------------------------------------------------------
// K4: A-resident pipelined sim+exp+rowsum, compare-free fast path.
// Grid (64 bi, 2 bhalf), 256 thr. Special tile per CTA:
//  - diag CTA (bhalf == bi>>5): tile t=bi&31 masks the diagonal exp.
//  - pos CTA (bhalf==1, bi<32): tile t=bi captures raw sim[gi][gi+4096] -> pos.
// Paired LDTM + single wait; exp2f with folded 10/ln2 constant.
// ---------------------------------------------------------------------------
__global__ void __launch_bounds__(256, 1) k_sim_rows(
    const __nv_bfloat16* __restrict__ Nh, float* __restrict__ part,
    float* __restrict__ pos)
{
    extern __shared__ __align__(16) char smem[];
    __shared__ float s_red[128][2];
    const int tid = threadIdx.x;
    const int bi = blockIdx.x, bhalf = blockIdx.y;
    const int ro = bi * 128;

#if HAS_TCGEN05
    const uint32_t smem_base = smem_to_u32(smem);
    const uint32_t aoff = ((smem_base + 1024 + 1023) & ~1023u) - smem_base;
    const uint32_t A_OFF = aoff;
    const uint32_t B_OFF0 = aoff + 65536;
    const uint32_t B_OFF1 = aoff + 131072;
    const uint32_t TPTR = 0, MBAR0 = 16, MBAR1 = 24;

    if (tid < 32) {
        TCGEN05_ALLOC(smem_base + TPTR, 256);
        TCGEN05_RELINQUISH();
    }
    if (tid == 0) { MBARRIER_INIT(smem_base + MBAR0, 1); MBARRIER_INIT(smem_base + MBAR1, 1); }
    __syncthreads();
    uint32_t tmem;
    asm volatile("ld.shared.b32 %0, [%1];" : "=r"(tmem) : "r"(smem_base + TPTR));
    const uint32_t D0 = tmem, D1 = tmem + 128;

    const __nv_bfloat16* Arows = Nh + (size_t)ro * PD;
    const __nv_bfloat16* Bbase = Nh + (size_t)(bhalf * HALF) * PD;

    // Hoisted addressing: absolute smem dsts for both B buffers + gmem offsets.
    uint32_t dstA[16], dst0[16], dst1[16], goff[16];
    #pragma unroll
    for (int it = 0; it < 16; it++) {
        int idx = tid + it * 256;
        int r = idx >> 5, q = idx & 31;
        uint32_t byte_off = (uint32_t)((r >> 3) + ((q >> 3) << 4)) * 1024u
                          + (uint32_t)(r & 7) * 128u + (uint32_t)(q & 7) * 16u;
        uint32_t sw = SW128(byte_off);
        dstA[it] = smem_base + A_OFF + sw;
        dst0[it] = smem_base + B_OFF0 + sw;
        dst1[it] = smem_base + B_OFF1 + sw;
        goff[it] = (uint32_t)(r * PD + q * 8);
    }

    // Prologue
    #pragma unroll
    for (int it = 0; it < 16; it++) {
        CP_ASYNC16(dstA[it], Arows + goff[it]);
        CP_ASYNC16(dst0[it], Bbase + goff[it]);
    }
    CP_COMMIT();
    #pragma unroll
    for (int it = 0; it < 16; it++)
        CP_ASYNC16(dst1[it], Bbase + 128 * PD + goff[it]);
    CP_COMMIT();
    CP_WAIT(1);
    __syncthreads();
    FENCE_PROXY_ASYNC();

    if (tid < 32) issue_tile_mma(D0, smem_base + A_OFF, smem_base + B_OFF0,
                                 smem_base + MBAR0);

    // Epilogue mapping: warp w -> rows (w&3)*32+lane, col half w>>2 (64 cols)
    const int w = tid >> 5, lane = tid & 31;
    const int row = (w & 3) * 32 + lane;
    const int chalf = w >> 2;
    const int gi = ro + row;

    // Special tile per CTA
    const bool sp_diag = (bhalf == (bi >> 5));
    const int t_sp = sp_diag ? (bi & 31) : ((bhalf == 1 && bi < 32) ? bi : -1);
    const int sp_col = sp_diag ? gi : gi + HALF;

    int ph0 = 0, ph1 = 0;
    float acc0 = 0.f, acc1 = 0.f, acc2 = 0.f, acc3 = 0.f;
    float posval = 0.f;

    for (int t = 0; t < 32; t++) {
        const int buf = t & 1;
        const uint32_t mb = smem_base + (buf ? MBAR1 : MBAR0);

        if (buf) { MBARRIER_WAIT_PARITY(mb, ph1); ph1 ^= 1; }
        else     { MBARRIER_WAIT_PARITY(mb, ph0); ph0 ^= 1; }

        if (t + 2 < 32) {
            const __nv_bfloat16* Brows = Bbase + (size_t)(t + 2) * 128 * PD;
            #pragma unroll
            for (int it = 0; it < 16; it++)
                CP_ASYNC16(buf ? dst1[it] : dst0[it], Brows + goff[it]);
        }
        CP_COMMIT();
        CP_WAIT(1);
        __syncthreads();
        FENCE_PROXY_ASYNC();
        TCGEN05_FENCE_AFTER();

        if (t + 1 < 32 && tid < 32)
            issue_tile_mma(buf ? D0 : D1, smem_base + A_OFF,
                           smem_base + (buf ? B_OFF0 : B_OFF1),
                           smem_base + (buf ? MBAR0 : MBAR1));

        const uint32_t dt = (buf ? D1 : D0) + chalf * 64;
        // Paired LDTM, single wait
        uint32_t r0[32], r1[32];
        TCGEN05_LD_32X32B_X32(r0, dt);
        TCGEN05_LD_32X32B_X32(r1, dt + 32);
        TCGEN05_WAIT_LD();

        if (t != t_sp) {
            // fast path: no compares, 4 accumulators, exp2 with folded scale
            #pragma unroll
            for (int j = 0; j < 32; j += 2) {
                acc0 += exp2f(L2E10 * __uint_as_float(r0[j]));
                acc1 += exp2f(L2E10 * __uint_as_float(r0[j + 1]));
                acc2 += exp2f(L2E10 * __uint_as_float(r1[j]));
                acc3 += exp2f(L2E10 * __uint_as_float(r1[j + 1]));
            }
        } else if (sp_diag) {
            const int jb = bhalf * HALF + t * 128 + chalf * 64;
            #pragma unroll
            for (int j = 0; j < 32; j++) {
                float e0 = exp2f(L2E10 * __uint_as_float(r0[j]));
                float e1 = exp2f(L2E10 * __uint_as_float(r1[j]));
                acc0 += (sp_col == jb + j) ? 0.0f : e0;
                acc1 += (sp_col == jb + 32 + j) ? 0.0f : e1;
            }
        } else {
            const int jb = bhalf * HALF + t * 128 + chalf * 64;
            #pragma unroll
            for (int j = 0; j < 32; j++) {
                float v0 = __uint_as_float(r0[j]);
                float v1 = __uint_as_float(r1[j]);
                acc0 += exp2f(L2E10 * v0);
                acc1 += exp2f(L2E10 * v1);
                if (sp_col == jb + j) posval = v0;
                if (sp_col == jb + 32 + j) posval = v1;
            }
        }
        TCGEN05_FENCE_BEFORE();
    }

    if (t_sp >= 0 && !sp_diag && (row >> 6) == chalf)
        pos[gi] = posval;

    s_red[row][chalf] = (acc0 + acc1) + (acc2 + acc3);
    __syncthreads();
    if (tid < 128)
        part[(size_t)bhalf * NROWS + ro + tid] = s_red[tid][0] + s_red[tid][1];

    __syncthreads();
    if (tid == 0) { MBARRIER_INVAL(smem_base + MBAR0); MBARRIER_INVAL(smem_base + MBAR1); }
    __syncthreads();
    if (tid < 32) TCGEN05_DEALLOC(tmem, 256);
#else
    // SIMT fallback (compile-only for the portable PTX pass)
    if (tid < 128) {
        const int gi = ro + tid;
        const __nv_bfloat16* arow = Nh + (size_t)gi * PD;
        float rowsum = 0.f;
        for (int j = 0; j < HALF; j++) {
            int gj = bhalf * HALF + j;
            const __nv_bfloat16* brow = Nh + (size_t)gj * PD;
            float s = 0.f;
            for (int k = 0; k < PD; k++)
                s += __bfloat162float(arow[k]) * __bfloat162float(brow[k]);
            rowsum += (gi == gj) ? 0.0f : __expf(10.0f * s);
        }
        part[(size_t)bhalf * NROWS + gi] = rowsum;
        if (bhalf == 1 && bi < 32) {
            const __nv_bfloat16* brow = Nh + (size_t)(gi + HALF) * PD;
            float s = 0.f;
            for (int k = 0; k < PD; k++)
                s += __bfloat162float(arow[k]) * __bfloat162float(brow[k]);
            pos[gi] = s;
        }
    }
#endif
}

// ---------------------------------------------------------------------------
// K6: parallel loss reduction (separate launch — overlaps better than fusion;
// R13 measured the fused variant 2 us SLOWER). Grid 64 x 256 threads.
// ---------------------------------------------------------------------------
__global__ void __launch_bounds__(256) k_loss(const float* __restrict__ part,
                                              const float* __restrict__ pos,
                                              float* __restrict__ lred,
                                              float* __restrict__ ppart,
                                              unsigned int* __restrict__ ctr,
                                              float* __restrict__ out)
{
    __shared__ float sh[256];
    __shared__ bool is_last;
    const int b = blockIdx.x;
    const int tid = threadIdx.x;

    float s = 0.f;
    if (tid < 128) {
        int i = b * 128 + tid;
        s = logf(part[i] + part[NROWS + i]);
    }
    float p = (tid < 64) ? pos[b * 64 + tid] : 0.f;

    sh[tid] = s;
    __syncthreads();
    #pragma unroll
    for (int o = 128; o > 0; o >>= 1) {
        if (tid < o) sh[tid] += sh[tid + o];
        __syncthreads();
    }
    float lsum = sh[0];
    __syncthreads();
    sh[tid] = p;
    __syncthreads();
    #pragma unroll
    for (int o = 128; o > 0; o >>= 1) {
        if (tid < o) sh[tid] += sh[tid + o];
        __syncthreads();
    }
    if (tid == 0) {
        lred[b]  = lsum;
        ppart[b] = sh[0];
        __threadfence();
        unsigned int old = atomicAdd(ctr, 1u);
        is_last = (old == 63u);
    }
    __syncthreads();

    if (is_last) {
        float lv = (tid < 64) ? lred[tid]  : 0.f;
        float pv = (tid < 64) ? ppart[tid] : 0.f;
        sh[tid] = lv;
        __syncthreads();
        #pragma unroll
        for (int o = 128; o > 0; o >>= 1) {
            if (tid < o) sh[tid] += sh[tid + o];
            __syncthreads();
        }
        float L = sh[0];
        __syncthreads();
        sh[tid] = pv;
        __syncthreads();
        #pragma unroll
        for (int o = 128; o > 0; o >>= 1) {
            if (tid < o) sh[tid] += sh[tid + o];
            __syncthreads();
        }
        if (tid == 0) {
            out[0] = (L - 20.0f * sh[0]) / (float)NROWS;
            *ctr = 0u;
        }
    }
}

// ---------------------------------------------------------------------------
extern "C" void kernel_launch(void* const* d_in, const int* in_sizes, int n_in,
                              void* d_out, int out_size)
{
    const float* X = (const float*)d_in[0];  // [8192, 2048]
    const float* W = (const float*)d_in[1];  // [2048, 256]
    const float* b = (const float*)d_in[2];  // [256]
    float* out = (float*)d_out;

    __nv_bfloat16* nrh;  cudaGetSymbolAddress((void**)&nrh,   g_normh);
    __nv_bfloat16* wt;   cudaGetSymbolAddress((void**)&wt,    g_Wt);
    float* part;         cudaGetSymbolAddress((void**)&part,  g_part);
    float* pos;          cudaGetSymbolAddress((void**)&pos,   g_pos);
    float* lred;         cudaGetSymbolAddress((void**)&lred,  g_lred);
    float* ppart;        cudaGetSymbolAddress((void**)&ppart, g_ppart);
    unsigned int* ctr;   cudaGetSymbolAddress((void**)&ctr,   g_ctr);

    const int SIM_SMEM  = 2048 + 3 * 65536;             // 198656 B
    const int GEMM_SMEM = 2048 + 2 * 32768 + 2 * 65536; // 198656 B
    cudaFuncSetAttribute(k_sim_rows,
                         cudaFuncAttributeMaxDynamicSharedMemorySize, SIM_SMEM);
    cudaFuncSetAttribute(k_gemm1_tc,
                         cudaFuncAttributeMaxDynamicSharedMemorySize, GEMM_SMEM);

    k_prep<<<dim3(32, 4), 256>>>(W, wt);
    k_gemm1_tc<<<64, 256, GEMM_SMEM>>>(X, wt, b, nrh);
    k_sim_rows<<<dim3(64, 2), 256, SIM_SMEM>>>(nrh, part, pos);
    k_loss<<<64, 256>>>(part, pos, lred, ppart, ctr, out);
}

// round 15
// speedup vs baseline: 1.0871x; 1.0307x over previous
#include <cuda_runtime.h>
#include <cuda_bf16.h>
#include <math.h>
#include <cstdint>

// Problem constants
#define NROWS 8192
#define HALF  4096
#define DIM   2048
#define PD    256
#define NT    64
#define L2E10 14.4269504088896340736f   // 10/ln2: exp(10x) = exp2(L2E10*x)

#if !defined(__CUDA_ARCH__) || defined(__CUDA_ARCH_FEAT_SM103_ALL) || defined(__CUDA_ARCH_FEAT_SM100_ALL)
#define HAS_TCGEN05 1
#else
#define HAS_TCGEN05 0
#endif

// Scratch (device globals; no allocation allowed)
__device__ __nv_bfloat16 g_normh[NROWS * PD];   // bf16 normalized (4 MB)
__device__ __nv_bfloat16 g_Wt[PD * DIM];        // W^T bf16 (1 MB)
__device__ float         g_part[2 * NROWS];     // rowsum halves (h=0/1)
__device__ float         g_cpart[32 * NROWS];   // colsum slots t=1..32 (1 MB)
__device__ float         g_pos[HALF];
__device__ float         g_lred[64];
__device__ float         g_ppart[64];
__device__ unsigned int  g_ctr;

// ---------------------------------------------------------------------------
// PTX helpers
// ---------------------------------------------------------------------------
__device__ __forceinline__ uint32_t smem_to_u32(const void* p) {
    uint32_t a;
    asm("{ .reg .u64 t; cvta.to.shared.u64 t, %1; cvt.u32.u64 %0, t; }"
        : "=r"(a) : "l"(p));
    return a;
}
__device__ __forceinline__ uint32_t elect_one_pred() {
    uint32_t pred;
    asm volatile("{\n\t.reg .pred p;\n\telect.sync _|p, 0xFFFFFFFF;\n\t"
                 "selp.b32 %0, 1, 0, p;\n\t}" : "=r"(pred));
    return pred;
}
#define TCGEN05_ALLOC(smem_addr, nCols) \
    asm volatile("tcgen05.alloc.cta_group::1.sync.aligned.shared::cta.b32 [%0], %1;" \
        :: "r"((uint32_t)(smem_addr)), "r"((uint32_t)(nCols)) : "memory")
#define TCGEN05_DEALLOC(tmem, nCols) \
    asm volatile("tcgen05.dealloc.cta_group::1.sync.aligned.b32 %0, %1;" \
        :: "r"(tmem), "r"((uint32_t)(nCols)))
#define TCGEN05_RELINQUISH() \
    asm volatile("tcgen05.relinquish_alloc_permit.cta_group::1.sync.aligned;")
#define TCGEN05_COMMIT(mbar) \
    asm volatile("tcgen05.commit.cta_group::1.mbarrier::arrive::one.shared::cluster.b64 [%0];" \
        :: "r"((uint32_t)(mbar)) : "memory")
#define TCGEN05_WAIT_LD()  asm volatile("tcgen05.wait::ld.sync.aligned;" ::: "memory")
#define TCGEN05_WAIT_ST()  asm volatile("tcgen05.wait::st.sync.aligned;" ::: "memory")
#define TCGEN05_FENCE_BEFORE() asm volatile("tcgen05.fence::before_thread_sync;" ::: "memory")
#define TCGEN05_FENCE_AFTER()  asm volatile("tcgen05.fence::after_thread_sync;" ::: "memory")
#define FENCE_PROXY_ASYNC() asm volatile("fence.proxy.async.shared::cta;" ::: "memory")
#define MBARRIER_INIT(mbar, cnt) \
    asm volatile("mbarrier.init.shared.b64 [%0], %1;" \
        :: "r"((uint32_t)(mbar)), "r"((uint32_t)(cnt)) : "memory")
#define MBARRIER_INVAL(mbar) \
    asm volatile("mbarrier.inval.shared.b64 [%0];" :: "r"((uint32_t)(mbar)) : "memory")
#define MBARRIER_WAIT_PARITY(mbar, par) do {                                     \
    uint32_t _m = (uint32_t)(mbar), _p = (uint32_t)(par), _d;                    \
    asm volatile("{\n\t.reg .pred p;\n\t"                                        \
        "mbarrier.try_wait.parity.acquire.cta.shared::cta.b64 p, [%1], %2;\n\t"  \
        "selp.b32 %0, 1, 0, p;\n\t}" : "=r"(_d) : "r"(_m), "r"(_p) : "memory");  \
    if (!_d) {                                                                   \
        asm volatile("{\n\t.reg .pred P1;\n\tWL_%=:\n\t"                         \
            "mbarrier.try_wait.parity.acquire.cta.shared::cta.b64 P1, [%0], %1, 0x989680;\n\t" \
            "@P1 bra.uni WD_%=;\n\tbra.uni WL_%=;\n\tWD_%=:\n\t}"                \
            :: "r"(_m), "r"(_p) : "memory");                                     \
    } } while (0)
#define TCGEN05_LD_32X32B_X32(r, tmem) \
    asm volatile("tcgen05.ld.sync.aligned.32x32b.x32.b32 " \
        "{%0, %1, %2, %3, %4, %5, %6, %7, %8, %9, %10, %11, %12, %13, %14, %15, " \
        "%16, %17, %18, %19, %20, %21, %22, %23, %24, %25, %26, %27, %28, %29, %30, %31}, [%32];" \
        : "=r"((r)[0]),  "=r"((r)[1]),  "=r"((r)[2]),  "=r"((r)[3]),  \
          "=r"((r)[4]),  "=r"((r)[5]),  "=r"((r)[6]),  "=r"((r)[7]),  \
          "=r"((r)[8]),  "=r"((r)[9]),  "=r"((r)[10]), "=r"((r)[11]), \
          "=r"((r)[12]), "=r"((r)[13]), "=r"((r)[14]), "=r"((r)[15]), \
          "=r"((r)[16]), "=r"((r)[17]), "=r"((r)[18]), "=r"((r)[19]), \
          "=r"((r)[20]), "=r"((r)[21]), "=r"((r)[22]), "=r"((r)[23]), \
          "=r"((r)[24]), "=r"((r)[25]), "=r"((r)[26]), "=r"((r)[27]), \
          "=r"((r)[28]), "=r"((r)[29]), "=r"((r)[30]), "=r"((r)[31]) \
        : "r"(tmem))
#define TCGEN05_ST_32X32B_X32(tmem, r) \
    asm volatile("tcgen05.st.sync.aligned.32x32b.x32.b32 [%0], " \
        "{%1, %2, %3, %4, %5, %6, %7, %8, %9, %10, %11, %12, %13, %14, %15, %16, " \
        "%17, %18, %19, %20, %21, %22, %23, %24, %25, %26, %27, %28, %29, %30, %31, %32};" \
        :: "r"(tmem), \
           "r"((r)[0]),  "r"((r)[1]),  "r"((r)[2]),  "r"((r)[3]),  \
           "r"((r)[4]),  "r"((r)[5]),  "r"((r)[6]),  "r"((r)[7]),  \
           "r"((r)[8]),  "r"((r)[9]),  "r"((r)[10]), "r"((r)[11]), \
           "r"((r)[12]), "r"((r)[13]), "r"((r)[14]), "r"((r)[15]), \
           "r"((r)[16]), "r"((r)[17]), "r"((r)[18]), "r"((r)[19]), \
           "r"((r)[20]), "r"((r)[21]), "r"((r)[22]), "r"((r)[23]), \
           "r"((r)[24]), "r"((r)[25]), "r"((r)[26]), "r"((r)[27]), \
           "r"((r)[28]), "r"((r)[29]), "r"((r)[30]), "r"((r)[31]) \
        : "memory")
#define CP_ASYNC16(smem_u32, gptr) \
    asm volatile("cp.async.cg.shared.global [%0], [%1], 16;" \
        :: "r"((uint32_t)(smem_u32)), "l"(gptr) : "memory")
#define CP_COMMIT() asm volatile("cp.async.commit_group;" ::: "memory")
#define CP_WAIT(n)  asm volatile("cp.async.wait_group %0;" :: "n"(n) : "memory")
// K-major SW128 desc: layout=2, ver=1, SBO=64, LBO=1
#define SMEM_DESC_BASE_SW128 \
    ((uint64_t(2) << 61) | (uint64_t(1) << 46) | (uint64_t(64) << 32) | (uint64_t(1) << 16))
#define MAKE_SMEM_DESC(addr) (SMEM_DESC_BASE_SW128 | ((uint64_t)((addr) >> 4) & 0x3FFF))
// MN-major SW128 desc (TransB operand): layout=2, ver=1, SBO=8, LBO=64
#define SMEM_DESC_BASE_SW128_MN \
    ((uint64_t(2) << 61) | (uint64_t(1) << 46) | (uint64_t(8) << 32) | (uint64_t(64) << 16))
#define MAKE_SMEM_DESC_MN(addr) (SMEM_DESC_BASE_SW128_MN | ((uint64_t)((addr) >> 4) & 0x3FFF))
#define SW128(off) ((off) ^ (((off) >> 3) & 0x70))

#if HAS_TCGEN05
__device__ __forceinline__ void mma_f16_ss(uint32_t d_tmem, uint64_t a_desc,
                                           uint64_t b_desc, uint32_t idesc,
                                           bool accum) {
    uint32_t en = accum ? 1u : 0u;
    asm volatile(
        "{\n\t.reg .pred p;\n\tsetp.ne.u32 p, %5, 0;\n\t"
        "tcgen05.mma.cta_group::1.kind::f16 [%0], %1, %2, %3, {%4, %4, %4, %4}, p;\n\t}"
        :: "r"(d_tmem), "l"(a_desc), "l"(b_desc), "r"(idesc), "r"(0u), "r"(en)
        : "memory");
}
// TS-mode (A in TMEM)
__device__ __forceinline__ void mma_f16_ts(uint32_t d_tmem, uint32_t a_tmem,
                                           uint64_t b_desc, uint32_t idesc,
                                           bool accum) {
    uint32_t en = accum ? 1u : 0u;
    asm volatile(
        "{\n\t.reg .pred p;\n\tsetp.ne.u32 p, %5, 0;\n\t"
        "tcgen05.mma.cta_group::1.kind::f16 [%0], [%1], %2, %3, {%4, %4, %4, %4}, p;\n\t}"
        :: "r"(d_tmem), "r"(a_tmem), "l"(b_desc), "r"(idesc), "r"(0u), "r"(en)
        : "memory");
}
#endif

// idescs: dtype F32, a/b BF16, M=128
#define SIM_IDESC  ((1u << 4) | (1u << 7) | (1u << 10) | ((128u / 8u) << 17) | ((128u / 16u) << 24))
#define GEMM_IDESC ((1u << 4) | (1u << 7) | (1u << 10) | ((256u / 8u) << 17) | ((128u / 16u) << 24))
// colsum MMA: N=64, TransB (bit 16)
#define CS_IDESC   ((1u << 4) | (1u << 7) | (1u << 10) | ((64u / 8u) << 17) | ((128u / 16u) << 24) | (1u << 16))

#if HAS_TCGEN05
// 16 chained K=16 MMAs, K=256, 128x256-bf16 SW128 tiles
__device__ __forceinline__ void issue_tile_mma(uint32_t d_tmem, uint32_t a_smem,
                                               uint32_t b_smem, uint32_t mbar) {
    uint64_t a_base = MAKE_SMEM_DESC(a_smem);
    uint64_t b_base = MAKE_SMEM_DESC(b_smem);
    if (elect_one_pred()) {
        #pragma unroll
        for (int s = 0; s < 16; s++) {
            uint64_t off = (uint64_t)((s >> 2) * 1024 + (s & 3) * 2);
            mma_f16_ss(d_tmem, a_base + off, b_base + off, SIM_IDESC, s > 0);
        }
        TCGEN05_COMMIT(mbar);
    }
}
__device__ __forceinline__ void g1_issue(uint32_t d_tmem, uint32_t a_smem,
                                         uint32_t b_smem, uint32_t mbar,
                                         bool first_chunk) {
    uint64_t a_base = MAKE_SMEM_DESC(a_smem);
    uint64_t b_base = MAKE_SMEM_DESC(b_smem);
    if (elect_one_pred()) {
        #pragma unroll
        for (int s = 0; s < 8; s++) {
            uint64_t offA = (uint64_t)((s >> 2) * 1024 + (s & 3) * 2);
            uint64_t offB = (uint64_t)((s >> 2) * 2048 + (s & 3) * 2);
            mma_f16_ss(d_tmem, a_base + offA, b_base + offB, GEMM_IDESC,
                       !(first_chunk && s == 0));
        }
        TCGEN05_COMMIT(mbar);
    }
}
__device__ __forceinline__ void g1_load_A(const float* __restrict__ X, int row0,
                                          int k0, char* smem, uint32_t A_OFF,
                                          int tid) {
    #pragma unroll
    for (int i = 0; i < 8; i++) {
        int u = tid + i * 256;
        int r = u >> 4, q = u & 15;
        const float* src = X + (size_t)(row0 + r) * DIM + k0 + q * 8;
        float4 v0 = *(const float4*)src;
        float4 v1 = *(const float4*)(src + 4);
        __nv_bfloat162 h2[4];
        h2[0] = __floats2bfloat162_rn(v0.x, v0.y);
        h2[1] = __floats2bfloat162_rn(v0.z, v0.w);
        h2[2] = __floats2bfloat162_rn(v1.x, v1.y);
        h2[3] = __floats2bfloat162_rn(v1.z, v1.w);
        uint32_t byte_off = (uint32_t)((r >> 3) + ((q >> 3) << 4)) * 1024u
                          + (uint32_t)(r & 7) * 128u + (uint32_t)(q & 7) * 16u;
        *(uint4*)(smem + A_OFF + SW128(byte_off)) = *(uint4*)h2;
    }
}
__device__ __forceinline__ void g1_load_B(const __nv_bfloat16* __restrict__ Wt,
                                          int k0, uint32_t smem_base,
                                          uint32_t B_OFF, int tid) {
    #pragma unroll
    for (int i = 0; i < 16; i++) {
        int u = tid + i * 256;
        int r = u >> 4, q = u & 15;
        uint32_t byte_off = (uint32_t)((r >> 3) + ((q >> 3) << 5)) * 1024u
                          + (uint32_t)(r & 7) * 128u + (uint32_t)(q & 7) * 16u;
        CP_ASYNC16(smem_base + B_OFF + SW128(byte_off),
                   Wt + (size_t)r * DIM + k0 + q * 8);
    }
}
#endif

// ---------------------------------------------------------------------------
// K0: Wt transpose + zero cpart slot 31 lower half (rows <4096 never written)
// ---------------------------------------------------------------------------
__global__ void __launch_bounds__(256) k_prep(const float* __restrict__ W,
                                              __nv_bfloat16* __restrict__ Wt,
                                              float* __restrict__ cpart)
{
    __shared__ float S[64][68];
    const int k0 = blockIdx.x * 64, n0 = blockIdx.y * 64;
    const int tid = threadIdx.x;

    if (blockIdx.y == 0 && blockIdx.x < 16)
        cpart[(size_t)31 * NROWS + blockIdx.x * 256 + tid] = 0.f;

    #pragma unroll
    for (int i = 0; i < 4; i++) {
        int t = tid + i * 256;
        int r = t >> 4, c4 = t & 15;
        float4 v = *(const float4*)&W[(size_t)(k0 + r) * PD + n0 + c4 * 4];
        S[r][c4 * 4 + 0] = v.x; S[r][c4 * 4 + 1] = v.y;
        S[r][c4 * 4 + 2] = v.z; S[r][c4 * 4 + 3] = v.w;
    }
    __syncthreads();
    #pragma unroll
    for (int i = 0; i < 2; i++) {
        int u = tid + i * 256;
        int n = u >> 3, ku = u & 7;
        __nv_bfloat162 h2[4];
        #pragma unroll
        for (int m = 0; m < 4; m++)
            h2[m] = __floats2bfloat162_rn(S[ku * 8 + 2 * m][n], S[ku * 8 + 2 * m + 1][n]);
        *(uint4*)&Wt[(size_t)(n0 + n) * DIM + k0 + ku * 8] = *(uint4*)h2;
    }
}

// ---------------------------------------------------------------------------
// K1: tcgen05 GEMM1 + bias + fused L2-normalize -> bf16. (unchanged)
// ---------------------------------------------------------------------------
__global__ void __launch_bounds__(256, 1) k_gemm1_tc(
    const float* __restrict__ X, const __nv_bfloat16* __restrict__ Wt,
    const float* __restrict__ b, __nv_bfloat16* __restrict__ Nh)
{
    extern __shared__ __align__(16) char smem[];
    __shared__ float s_red[128][2];
    __shared__ float s_bias[256];

    const int tid = threadIdx.x;
    const int row0 = blockIdx.x * 128;
    s_bias[tid] = b[tid];

#if HAS_TCGEN05
    const uint32_t smem_base = smem_to_u32(smem);
    const uint32_t aoff = ((smem_base + 1024 + 1023) & ~1023u) - smem_base;
    const uint32_t A_OFF0 = aoff;
    const uint32_t A_OFF1 = aoff + 32768;
    const uint32_t B_OFF0 = aoff + 65536;
    const uint32_t B_OFF1 = aoff + 131072;
    const uint32_t TPTR = 0, MB0 = 16, MB1 = 24;

    if (tid < 32) {
        TCGEN05_ALLOC(smem_base + TPTR, 256);
        TCGEN05_RELINQUISH();
    }
    if (tid == 0) { MBARRIER_INIT(smem_base + MB0, 1); MBARRIER_INIT(smem_base + MB1, 1); }
    __syncthreads();
    uint32_t tmem;
    asm volatile("ld.shared.b32 %0, [%1];" : "=r"(tmem) : "r"(smem_base + TPTR));

    g1_load_B(Wt, 0, smem_base, B_OFF0, tid);
    CP_COMMIT();
    g1_load_A(X, row0, 0, smem, A_OFF0, tid);
    CP_WAIT(0);
    __syncthreads();
    FENCE_PROXY_ASYNC();

    int ph0 = 0, ph1 = 0;
    for (int c = 0; c < 16; c++) {
        const int buf = c & 1;
        if (tid < 32)
            g1_issue(tmem, smem_base + (buf ? A_OFF1 : A_OFF0),
                     smem_base + (buf ? B_OFF1 : B_OFF0),
                     smem_base + (buf ? MB1 : MB0), c == 0);
        if (c + 1 < 16) {
            if (c >= 1) {
                if (buf) { MBARRIER_WAIT_PARITY(smem_base + MB0, ph0); ph0 ^= 1; }
                else     { MBARRIER_WAIT_PARITY(smem_base + MB1, ph1); ph1 ^= 1; }
            }
            g1_load_B(Wt, (c + 1) * 128, smem_base, buf ? B_OFF0 : B_OFF1, tid);
            CP_COMMIT();
            g1_load_A(X, row0, (c + 1) * 128, smem, buf ? A_OFF0 : A_OFF1, tid);
            CP_WAIT(0);
            __syncthreads();
            FENCE_PROXY_ASYNC();
        }
    }
    MBARRIER_WAIT_PARITY(smem_base + MB1, ph1);
    TCGEN05_FENCE_AFTER();

    const int w = tid >> 5, lane = tid & 31;
    const int row = (w & 3) * 32 + lane;
    const int half = w >> 2;
    const uint32_t tbase = tmem + half * 128;

    float sumsq = 0.f;
    #pragma unroll
    for (int c8 = 0; c8 < 2; c8++) {
        uint32_t r0[32], r1[32];
        TCGEN05_LD_32X32B_X32(r0, tbase + c8 * 64);
        TCGEN05_LD_32X32B_X32(r1, tbase + c8 * 64 + 32);
        TCGEN05_WAIT_LD();
        #pragma unroll
        for (int j = 0; j < 32; j++) {
            float v0 = __uint_as_float(r0[j]) + s_bias[half * 128 + c8 * 64 + j];
            float v1 = __uint_as_float(r1[j]) + s_bias[half * 128 + c8 * 64 + 32 + j];
            sumsq += v0 * v0 + v1 * v1;
        }
    }
    s_red[row][half] = sumsq;
    __syncthreads();
    float inv = 1.0f / fmaxf(sqrtf(s_red[row][0] + s_red[row][1]), 1e-12f);

    const size_t gbase = (size_t)(row0 + row) * PD + half * 128;
    #pragma unroll
    for (int c8 = 0; c8 < 2; c8++) {
        uint32_t r0[32], r1[32];
        TCGEN05_LD_32X32B_X32(r0, tbase + c8 * 64);
        TCGEN05_LD_32X32B_X32(r1, tbase + c8 * 64 + 32);
        TCGEN05_WAIT_LD();
        float v[64];
        #pragma unroll
        for (int j = 0; j < 32; j++) {
            v[j]      = (__uint_as_float(r0[j]) + s_bias[half * 128 + c8 * 64 + j]) * inv;
            v[32 + j] = (__uint_as_float(r1[j]) + s_bias[half * 128 + c8 * 64 + 32 + j]) * inv;
        }
        __nv_bfloat162 hh[32];
        #pragma unroll
        for (int j2 = 0; j2 < 32; j2++)
            hh[j2] = __floats2bfloat162_rn(v[2 * j2], v[2 * j2 + 1]);
        #pragma unroll
        for (int q = 0; q < 8; q++)
            *(uint4*)&Nh[gbase + c8 * 64 + q * 8] = ((uint4*)hh)[q];
    }
    TCGEN05_FENCE_BEFORE();

    __syncthreads();
    if (tid == 0) { MBARRIER_INVAL(smem_base + MB0); MBARRIER_INVAL(smem_base + MB1); }
    __syncthreads();
    if (tid < 32) TCGEN05_DEALLOC(tmem, 256);
#else
    const int row = row0 + (tid & 127);
    if (tid < 128) {
        float sumsq = 0.f;
        for (int n = 0; n < PD; n++) {
            float s = 0.f;
            for (int k = 0; k < DIM; k++)
                s += X[(size_t)row * DIM + k] * __bfloat162float(Wt[(size_t)n * DIM + k]);
            s += s_bias[n];
            sumsq += s * s;
        }
        float inv = 1.0f / fmaxf(sqrtf(sumsq), 1e-12f);
        for (int n = 0; n < PD; n++) {
            float s = 0.f;
            for (int k = 0; k < DIM; k++)
                s += X[(size_t)row * DIM + k] * __bfloat162float(Wt[(size_t)n * DIM + k]);
            Nh[(size_t)row * PD + n] = __float2bfloat16((s + s_bias[n]) * inv);
        }
    }
#endif
}

// ---------------------------------------------------------------------------
// K4: SYMMETRIC pipelined sim. Grid (64 bi, 2 h), 256 thr.
// CTA (i,h): A_i resident, tiles t in [h*16, h*16+16) (+t=32 for i<32,h=1),
// col block j=(i+t)%64. Row sums in regs -> part[h]. Col sums via staged
// bf16 E tile (MN-major SW128, two 64-col panels) + ones TS-MMA -> cpart[t-1].
// t=0 = diagonal tile (masked); t=32 carries pos pairs.
// ---------------------------------------------------------------------------
__global__ void __launch_bounds__(256, 1) k_sim_sym(
    const __nv_bfloat16* __restrict__ Nh, float* __restrict__ part,
    float* __restrict__ cpart, float* __restrict__ pos)
{
    extern __shared__ __align__(16) char smem[];
    const int tid = threadIdx.x;
    const int bi = blockIdx.x, h = blockIdx.y;
    const int ro = bi * 128;

#if HAS_TCGEN05
    const uint32_t smem_base = smem_to_u32(smem);
    const uint32_t aoff = ((smem_base + 1024 + 1023) & ~1023u) - smem_base;
    const uint32_t A_OFF  = aoff;
    const uint32_t B_OFF0 = aoff + 65536;
    const uint32_t B_OFF1 = aoff + 131072;
    const uint32_t E_OFF  = aoff + 196608;   // 32 KB: 2 panels x 16 KB
    const uint32_t TPTR = 0, MBAR0 = 16, MBAR1 = 24, MBAR2 = 32, CS_OFF = 64;
    float* csf = (float*)(smem + CS_OFF);    // 128 floats inside ctrl region

    const int t0 = h ? 16 : 0;
    const int Tend = h ? ((bi < 32) ? 32 : 31) : 15;
    const int tcs0 = h ? 16 : 1;             // first colsum tile

    if (tid < 32) { TCGEN05_ALLOC(smem_base + TPTR, 512); TCGEN05_RELINQUISH(); }
    if (tid == 0) {
        MBARRIER_INIT(smem_base + MBAR0, 1);
        MBARRIER_INIT(smem_base + MBAR1, 1);
        MBARRIER_INIT(smem_base + MBAR2, 1);
    }
    __syncthreads();
    uint32_t tmem;
    asm volatile("ld.shared.b32 %0, [%1];" : "=r"(tmem) : "r"(smem_base + TPTR));
    const uint32_t D0 = tmem, D1 = tmem + 128, D2 = tmem + 256, AONES = tmem + 384;

    // ones (bf16 1.0 pairs) into TMEM A operand: 128 lanes x 64 cols
    if (tid < 128) {
        uint32_t ones[32];
        #pragma unroll
        for (int k2 = 0; k2 < 32; k2++) ones[k2] = 0x3F803F80u;
        uint32_t woff = ((uint32_t)(tid >> 5)) << 21;
        TCGEN05_ST_32X32B_X32(AONES + woff, ones);
        TCGEN05_ST_32X32B_X32(AONES + woff + 32, ones);
        TCGEN05_WAIT_ST();
    }
    TCGEN05_FENCE_BEFORE();

    // Hoisted cp.async addressing
    uint32_t dstA[16], dst0[16], dst1[16], goff[16];
    #pragma unroll
    for (int it = 0; it < 16; it++) {
        int idx = tid + it * 256;
        int r = idx >> 5, q = idx & 31;
        uint32_t byte_off = (uint32_t)((r >> 3) + ((q >> 3) << 4)) * 1024u
                          + (uint32_t)(r & 7) * 128u + (uint32_t)(q & 7) * 16u;
        uint32_t sw = SW128(byte_off);
        dstA[it] = smem_base + A_OFF + sw;
        dst0[it] = smem_base + B_OFF0 + sw;
        dst1[it] = smem_base + B_OFF1 + sw;
        goff[it] = (uint32_t)(r * PD + q * 8);
    }

    // Epilogue mapping + hoisted E staging addresses
    const int w = tid >> 5, lane = tid & 31;
    const int row = (w & 3) * 32 + lane;
    const int chalf = w >> 2;
    const int gi = ro + row;
    uint32_t eaddr[8];
    #pragma unroll
    for (int u = 0; u < 8; u++) {
        uint32_t byte_off = (uint32_t)(row >> 3) * 1024u + (uint32_t)(row & 7) * 128u
                          + (uint32_t)u * 16u;
        eaddr[u] = smem_base + E_OFF + (uint32_t)chalf * 16384u + SW128(byte_off);
    }

    // Prologue loads: A + B(t0), B(t0+1)
    {
        const __nv_bfloat16* Arows = Nh + (size_t)ro * PD;
        const __nv_bfloat16* B0r = Nh + (size_t)(((bi + t0) & 63) * 128) * PD;
        const __nv_bfloat16* B1r = Nh + (size_t)(((bi + t0 + 1) & 63) * 128) * PD;
        #pragma unroll
        for (int it = 0; it < 16; it++) {
            CP_ASYNC16(dstA[it], Arows + goff[it]);
            CP_ASYNC16(dst0[it], B0r + goff[it]);
        }
        CP_COMMIT();
        #pragma unroll
        for (int it = 0; it < 16; it++)
            CP_ASYNC16(dst1[it], B1r + goff[it]);
        CP_COMMIT();
    }
    CP_WAIT(1);
    __syncthreads();
    FENCE_PROXY_ASYNC();

    if (tid < 32) issue_tile_mma(D0, smem_base + A_OFF, smem_base + B_OFF0,
                                 smem_base + MBAR0);

    int ph0 = 0, ph1 = 0, ph2 = 0;
    float acc0 = 0.f, acc1 = 0.f, acc2 = 0.f, acc3 = 0.f;
    float posval = 0.f;
    const uint64_t e_desc0 = MAKE_SMEM_DESC_MN(smem_base + E_OFF);
    const uint64_t e_desc1 = MAKE_SMEM_DESC_MN(smem_base + E_OFF + 16384);

    for (int t = t0; t <= Tend; t++) {
        const int buf = t & 1;
        // 1. wait sim MMA(t)
        if (buf) { MBARRIER_WAIT_PARITY(smem_base + MBAR1, ph1); ph1 ^= 1; }
        else     { MBARRIER_WAIT_PARITY(smem_base + MBAR0, ph0); ph0 ^= 1; }
        // 2. prefetch B(t+2)
        if (t + 2 <= Tend) {
            const __nv_bfloat16* Br = Nh + (size_t)(((bi + t + 2) & 63) * 128) * PD;
            #pragma unroll
            for (int it = 0; it < 16; it++)
                CP_ASYNC16(buf ? dst1[it] : dst0[it], Br + goff[it]);
        }
        CP_COMMIT();
        CP_WAIT(1);
        __syncthreads();
        FENCE_PROXY_ASYNC();
        TCGEN05_FENCE_AFTER();
        // 3. issue sim MMA(t+1)
        if (t + 1 <= Tend && tid < 32)
            issue_tile_mma(buf ? D0 : D1, smem_base + A_OFF,
                           smem_base + (buf ? B_OFF0 : B_OFF1),
                           smem_base + (buf ? MBAR0 : MBAR1));
        // 4. colsum readback for tile t-1
        const bool havep = (t - 1 >= tcs0);
        if (havep) {
            MBARRIER_WAIT_PARITY(smem_base + MBAR2, ph2); ph2 ^= 1;
            TCGEN05_FENCE_AFTER();
            if (w < 4) {
                uint32_t rr[32];
                TCGEN05_LD_32X32B_X32(rr, D2 + w * 32);
                TCGEN05_WAIT_LD();
                if (lane == 0) {
                    #pragma unroll
                    for (int k2 = 0; k2 < 32; k2++)
                        csf[w * 32 + k2] = __uint_as_float(rr[k2]);
                }
            }
        }
        // 5. epilogue on D[buf]: exp + rowsum + bf16 E staging
        const uint32_t dt = (buf ? D1 : D0) + chalf * 64;
        uint32_t r0[32], r1[32];
        TCGEN05_LD_32X32B_X32(r0, dt);
        TCGEN05_LD_32X32B_X32(r1, dt + 32);
        TCGEN05_WAIT_LD();

        if (t == 0) {
            // diagonal tile: mask, no staging/colsum
            const int cb = chalf * 64;
            #pragma unroll
            for (int j = 0; j < 32; j++) {
                float e0 = exp2f(L2E10 * __uint_as_float(r0[j]));
                float e1 = exp2f(L2E10 * __uint_as_float(r1[j]));
                acc0 += (cb + j == row) ? 0.0f : e0;
                acc1 += (cb + 32 + j == row) ? 0.0f : e1;
            }
        } else if (t == 32) {
            // pos tile: capture raw diag value, full sums + staging
            const int cb = chalf * 64;
            #pragma unroll
            for (int u = 0; u < 4; u++) {
                __nv_bfloat162 hp[4];
                #pragma unroll
                for (int m = 0; m < 4; m++) {
                    int j = u * 8 + 2 * m;
                    float va = __uint_as_float(r0[j]);
                    float vb = __uint_as_float(r0[j + 1]);
                    if (cb + j == row) posval = va;
                    if (cb + j + 1 == row) posval = vb;
                    float ea = exp2f(L2E10 * va), eb = exp2f(L2E10 * vb);
                    acc0 += ea; acc1 += eb;
                    hp[m] = __floats2bfloat162_rn(ea, eb);
                }
                *(uint4*)(uintptr_t)0; // placeholder removed below
                *(uint4*)((char*)smem + (eaddr[u] - smem_base)) = *(uint4*)hp;
            }
            #pragma unroll
            for (int u = 0; u < 4; u++) {
                __nv_bfloat162 hp[4];
                #pragma unroll
                for (int m = 0; m < 4; m++) {
                    int j = u * 8 + 2 * m;
                    float va = __uint_as_float(r1[j]);
                    float vb = __uint_as_float(r1[j + 1]);
                    if (cb + 32 + j == row) posval = va;
                    if (cb + 32 + j + 1 == row) posval = vb;
                    float ea = exp2f(L2E10 * va), eb = exp2f(L2E10 * vb);
                    acc2 += ea; acc3 += eb;
                    hp[m] = __floats2bfloat162_rn(ea, eb);
                }
                *(uint4*)((char*)smem + (eaddr[4 + u] - smem_base)) = *(uint4*)hp;
            }
        } else {
            // fast path: no compares, stage + accumulate
            #pragma unroll
            for (int u = 0; u < 4; u++) {
                __nv_bfloat162 hp[4];
                #pragma unroll
                for (int m = 0; m < 4; m++) {
                    int j = u * 8 + 2 * m;
                    float ea = exp2f(L2E10 * __uint_as_float(r0[j]));
                    float eb = exp2f(L2E10 * __uint_as_float(r0[j + 1]));
                    acc0 += ea; acc1 += eb;
                    hp[m] = __floats2bfloat162_rn(ea, eb);
                }
                *(uint4*)((char*)smem + (eaddr[u] - smem_base)) = *(uint4*)hp;
            }
            #pragma unroll
            for (int u = 0; u < 4; u++) {
                __nv_bfloat162 hp[4];
                #pragma unroll
                for (int m = 0; m < 4; m++) {
                    int j = u * 8 + 2 * m;
                    float ea = exp2f(L2E10 * __uint_as_float(r1[j]));
                    float eb = exp2f(L2E10 * __uint_as_float(r1[j + 1]));
                    acc2 += ea; acc3 += eb;
                    hp[m] = __floats2bfloat162_rn(ea, eb);
                }
                *(uint4*)((char*)smem + (eaddr[4 + u] - smem_base)) = *(uint4*)hp;
            }
        }
        TCGEN05_FENCE_BEFORE();
        __syncthreads();          // E staged + csf visible
        FENCE_PROXY_ASYNC();      // order generic E stores before async MMA read
        // 6. write colsums of tile t-1 (coalesced)
        if (havep && tid < 128) {
            int jprev = (bi + (t - 1)) & 63;
            cpart[(size_t)(t - 2) * NROWS + jprev * 128 + tid] = csf[tid];
        }
        // 7. issue colsum MMA for tile t
        if (t >= tcs0 && tid < 32 && elect_one_pred()) {
            #pragma unroll
            for (int s = 0; s < 8; s++)
                mma_f16_ts(D2, AONES + s * 8, e_desc0 + (uint64_t)s * 128, CS_IDESC, s > 0);
            #pragma unroll
            for (int s = 0; s < 8; s++)
                mma_f16_ts(D2 + 64, AONES + s * 8, e_desc1 + (uint64_t)s * 128, CS_IDESC, s > 0);
            TCGEN05_COMMIT(smem_base + MBAR2);
        }
    }

    // drain last colsum (tile Tend)
    MBARRIER_WAIT_PARITY(smem_base + MBAR2, ph2);
    TCGEN05_FENCE_AFTER();
    if (w < 4) {
        uint32_t rr[32];
        TCGEN05_LD_32X32B_X32(rr, D2 + w * 32);
        TCGEN05_WAIT_LD();
        if (lane == 0) {
            #pragma unroll
            for (int k2 = 0; k2 < 32; k2++) csf[w * 32 + k2] = __uint_as_float(rr[k2]);
        }
    }
    TCGEN05_FENCE_BEFORE();
    __syncthreads();
    if (tid < 128) {
        int jl = (bi + Tend) & 63;
        cpart[(size_t)(Tend - 1) * NROWS + jl * 128 + tid] = csf[tid];
    }

    // rowsum cross-chalf reduce via (now free) E area
    {
        float* red = (float*)(smem + E_OFF);
        red[row * 2 + chalf] = (acc0 + acc1) + (acc2 + acc3);
        __syncthreads();
        if (tid < 128)
            part[(size_t)h * NROWS + ro + tid] = red[tid * 2] + red[tid * 2 + 1];
    }
    if (h == 1 && bi < 32 && (row >> 6) == chalf)
        pos[gi] = posval;

    __syncthreads();
    if (tid == 0) {
        MBARRIER_INVAL(smem_base + MBAR0);
        MBARRIER_INVAL(smem_base + MBAR1);
        MBARRIER_INVAL(smem_base + MBAR2);
    }
    __syncthreads();
    if (tid < 32) TCGEN05_DEALLOC(tmem, 512);
#else
    // SIMT fallback (compile-only; never executed on GB300)
    if (tid < 128) {
        const int gi2 = ro + tid;
        const int T0 = h ? 16 : 0;
        const int T1 = h ? ((bi < 32) ? 32 : 31) : 15;
        const __nv_bfloat16* arow = Nh + (size_t)gi2 * PD;
        float rowsum = 0.f, pv = 0.f;
        for (int t = T0; t <= T1; t++) {
            int j = (bi + t) & 63;
            for (int c = 0; c < 128; c++) {
                int gc = j * 128 + c;
                const __nv_bfloat16* brow = Nh + (size_t)gc * PD;
                float s = 0.f;
                for (int k = 0; k < PD; k++)
                    s += __bfloat162float(arow[k]) * __bfloat162float(brow[k]);
                float e = __expf(10.0f * s);
                if (t == 0 && gc == gi2) e = 0.f;
                if (t == 32 && gc == gi2 + HALF) pv = s;
                rowsum += e;
            }
            if (t >= 1) {
                int gc = j * 128 + tid;
                const __nv_bfloat16* brow = Nh + (size_t)gc * PD;
                float cs = 0.f;
                for (int r2 = 0; r2 < 128; r2++) {
                    const __nv_bfloat16* ar = Nh + (size_t)(ro + r2) * PD;
                    float s = 0.f;
                    for (int k = 0; k < PD; k++)
                        s += __bfloat162float(ar[k]) * __bfloat162float(brow[k]);
                    cs += __expf(10.0f * s);
                }
                cpart[(size_t)(t - 1) * NROWS + gc] = cs;
            }
        }
        part[(size_t)h * NROWS + gi2] = rowsum;
        if (h == 1 && bi < 32) pos[gi2] = pv;
    }
#endif
}

// ---------------------------------------------------------------------------
// K6: parallel loss. neg_i = part0+part1 + 31/32 cpart slots (fixed order).
// ---------------------------------------------------------------------------
__global__ void __launch_bounds__(256) k_loss(const float* __restrict__ part,
                                              const float* __restrict__ cpart,
                                              const float* __restrict__ pos,
                                              float* __restrict__ lred,
                                              float* __restrict__ ppart,
                                              unsigned int* __restrict__ ctr,
                                              float* __restrict__ out)
{
    __shared__ float sh[256];
    __shared__ bool is_last;
    const int b = blockIdx.x;
    const int tid = threadIdx.x;

    float s = 0.f;
    if (tid < 128) {
        int gi = b * 128 + tid;
        float neg = part[gi] + part[NROWS + gi];
        #pragma unroll 4
        for (int s2 = 0; s2 < 31; s2++) neg += cpart[(size_t)s2 * NROWS + gi];
        if (gi >= HALF) neg += cpart[(size_t)31 * NROWS + gi];
        s = logf(neg);
    }
    float p = (tid < 64) ? pos[b * 64 + tid] : 0.f;

    sh[tid] = s;
    __syncthreads();
    #pragma unroll
    for (int o = 128; o > 0; o >>= 1) {
        if (tid < o) sh[tid] += sh[tid + o];
        __syncthreads();
    }
    float lsum = sh[0];
    __syncthreads();
    sh[tid] = p;
    __syncthreads();
    #pragma unroll
    for (int o = 128; o > 0; o >>= 1) {
        if (tid < o) sh[tid] += sh[tid + o];
        __syncthreads();
    }
    if (tid == 0) {
        lred[b]  = lsum;
        ppart[b] = sh[0];
        __threadfence();
        unsigned int old = atomicAdd(ctr, 1u);
        is_last = (old == 63u);
    }
    __syncthreads();

    if (is_last) {
        float lv = (tid < 64) ? lred[tid]  : 0.f;
        float pv = (tid < 64) ? ppart[tid] : 0.f;
        sh[tid] = lv;
        __syncthreads();
        #pragma unroll
        for (int o = 128; o > 0; o >>= 1) {
            if (tid < o) sh[tid] += sh[tid + o];
            __syncthreads();
        }
        float L = sh[0];
        __syncthreads();
        sh[tid] = pv;
        __syncthreads();
        #pragma unroll
        for (int o = 128; o > 0; o >>= 1) {
            if (tid < o) sh[tid] += sh[tid + o];
            __syncthreads();
        }
        if (tid == 0) {
            out[0] = (L - 20.0f * sh[0]) / (float)NROWS;
            *ctr = 0u;
        }
    }
}

// ---------------------------------------------------------------------------
extern "C" void kernel_launch(void* const* d_in, const int* in_sizes, int n_in,
                              void* d_out, int out_size)
{
    const float* X = (const float*)d_in[0];  // [8192, 2048]
    const float* W = (const float*)d_in[1];  // [2048, 256]
    const float* b = (const float*)d_in[2];  // [256]
    float* out = (float*)d_out;

    __nv_bfloat16* nrh;  cudaGetSymbolAddress((void**)&nrh,   g_normh);
    __nv_bfloat16* wt;   cudaGetSymbolAddress((void**)&wt,    g_Wt);
    float* part;         cudaGetSymbolAddress((void**)&part,  g_part);
    float* cpart;        cudaGetSymbolAddress((void**)&cpart, g_cpart);
    float* pos;          cudaGetSymbolAddress((void**)&pos,   g_pos);
    float* lred;         cudaGetSymbolAddress((void**)&lred,  g_lred);
    float* ppart;        cudaGetSymbolAddress((void**)&ppart, g_ppart);
    unsigned int* ctr;   cudaGetSymbolAddress((void**)&ctr,   g_ctr);

    const int SIM_SMEM  = 1024 + 1024 + 3 * 65536 + 32768;  // 231424 B
    const int GEMM_SMEM = 2048 + 2 * 32768 + 2 * 65536;     // 198656 B
    cudaFuncSetAttribute(k_sim_sym,
                         cudaFuncAttributeMaxDynamicSharedMemorySize, SIM_SMEM);
    cudaFuncSetAttribute(k_gemm1_tc,
                         cudaFuncAttributeMaxDynamicSharedMemorySize, GEMM_SMEM);

    k_prep<<<dim3(32, 4), 256>>>(W, wt, cpart);
    k_gemm1_tc<<<64, 256, GEMM_SMEM>>>(X, wt, b, nrh);
    k_sim_sym<<<dim3(64, 2), 256, SIM_SMEM>>>(nrh, part, cpart, pos);
    k_loss<<<64, 256>>>(part, cpart, pos, lred, ppart, ctr, out);
}

// round 16
// speedup vs baseline: 1.1201x; 1.0304x over previous
#include <cuda_runtime.h>
#include <cuda_bf16.h>
#include <math.h>
#include <cstdint>

// Problem constants
#define NROWS 8192
#define HALF  4096
#define DIM   2048
#define PD    256
#define NT    64
#define L2E10 14.4269504088896340736f   // 10/ln2: exp(10x) = exp2(L2E10*x)

#if !defined(__CUDA_ARCH__) || defined(__CUDA_ARCH_FEAT_SM103_ALL) || defined(__CUDA_ARCH_FEAT_SM100_ALL)
#define HAS_TCGEN05 1
#else
#define HAS_TCGEN05 0
#endif

// Scratch (device globals; no allocation allowed)
__device__ __nv_bfloat16 g_normh[NROWS * PD];   // bf16 normalized (4 MB)
__device__ __nv_bfloat16 g_Wt[PD * DIM];        // W^T bf16 (1 MB)
__device__ float         g_part[2 * NROWS];     // rowsum halves (h=0/1)
__device__ float         g_cpart[32 * NROWS];   // colsum slots t=1..32 (1 MB)
__device__ float         g_pos[HALF];
__device__ float         g_lred[256];
__device__ float         g_ppart[256];
__device__ unsigned int  g_ctr;

// ---------------------------------------------------------------------------
// PTX helpers
// ---------------------------------------------------------------------------
__device__ __forceinline__ uint32_t smem_to_u32(const void* p) {
    uint32_t a;
    asm("{ .reg .u64 t; cvta.to.shared.u64 t, %1; cvt.u32.u64 %0, t; }"
        : "=r"(a) : "l"(p));
    return a;
}
__device__ __forceinline__ uint32_t elect_one_pred() {
    uint32_t pred;
    asm volatile("{\n\t.reg .pred p;\n\telect.sync _|p, 0xFFFFFFFF;\n\t"
                 "selp.b32 %0, 1, 0, p;\n\t}" : "=r"(pred));
    return pred;
}
#define TCGEN05_ALLOC(smem_addr, nCols) \
    asm volatile("tcgen05.alloc.cta_group::1.sync.aligned.shared::cta.b32 [%0], %1;" \
        :: "r"((uint32_t)(smem_addr)), "r"((uint32_t)(nCols)) : "memory")
#define TCGEN05_DEALLOC(tmem, nCols) \
    asm volatile("tcgen05.dealloc.cta_group::1.sync.aligned.b32 %0, %1;" \
        :: "r"(tmem), "r"((uint32_t)(nCols)))
#define TCGEN05_RELINQUISH() \
    asm volatile("tcgen05.relinquish_alloc_permit.cta_group::1.sync.aligned;")
#define TCGEN05_COMMIT(mbar) \
    asm volatile("tcgen05.commit.cta_group::1.mbarrier::arrive::one.shared::cluster.b64 [%0];" \
        :: "r"((uint32_t)(mbar)) : "memory")
#define TCGEN05_WAIT_LD()  asm volatile("tcgen05.wait::ld.sync.aligned;" ::: "memory")
#define TCGEN05_WAIT_ST()  asm volatile("tcgen05.wait::st.sync.aligned;" ::: "memory")
#define TCGEN05_FENCE_BEFORE() asm volatile("tcgen05.fence::before_thread_sync;" ::: "memory")
#define TCGEN05_FENCE_AFTER()  asm volatile("tcgen05.fence::after_thread_sync;" ::: "memory")
#define FENCE_PROXY_ASYNC() asm volatile("fence.proxy.async.shared::cta;" ::: "memory")
#define MBARRIER_INIT(mbar, cnt) \
    asm volatile("mbarrier.init.shared.b64 [%0], %1;" \
        :: "r"((uint32_t)(mbar)), "r"((uint32_t)(cnt)) : "memory")
#define MBARRIER_INVAL(mbar) \
    asm volatile("mbarrier.inval.shared.b64 [%0];" :: "r"((uint32_t)(mbar)) : "memory")
#define MBARRIER_WAIT_PARITY(mbar, par) do {                                     \
    uint32_t _m = (uint32_t)(mbar), _p = (uint32_t)(par), _d;                    \
    asm volatile("{\n\t.reg .pred p;\n\t"                                        \
        "mbarrier.try_wait.parity.acquire.cta.shared::cta.b64 p, [%1], %2;\n\t"  \
        "selp.b32 %0, 1, 0, p;\n\t}" : "=r"(_d) : "r"(_m), "r"(_p) : "memory");  \
    if (!_d) {                                                                   \
        asm volatile("{\n\t.reg .pred P1;\n\tWL_%=:\n\t"                         \
            "mbarrier.try_wait.parity.acquire.cta.shared::cta.b64 P1, [%0], %1, 0x989680;\n\t" \
            "@P1 bra.uni WD_%=;\n\tbra.uni WL_%=;\n\tWD_%=:\n\t}"                \
            :: "r"(_m), "r"(_p) : "memory");                                     \
    } } while (0)
#define TCGEN05_LD_32X32B_X32(r, tmem) \
    asm volatile("tcgen05.ld.sync.aligned.32x32b.x32.b32 " \
        "{%0, %1, %2, %3, %4, %5, %6, %7, %8, %9, %10, %11, %12, %13, %14, %15, " \
        "%16, %17, %18, %19, %20, %21, %22, %23, %24, %25, %26, %27, %28, %29, %30, %31}, [%32];" \
        : "=r"((r)[0]),  "=r"((r)[1]),  "=r"((r)[2]),  "=r"((r)[3]),  \
          "=r"((r)[4]),  "=r"((r)[5]),  "=r"((r)[6]),  "=r"((r)[7]),  \
          "=r"((r)[8]),  "=r"((r)[9]),  "=r"((r)[10]), "=r"((r)[11]), \
          "=r"((r)[12]), "=r"((r)[13]), "=r"((r)[14]), "=r"((r)[15]), \
          "=r"((r)[16]), "=r"((r)[17]), "=r"((r)[18]), "=r"((r)[19]), \
          "=r"((r)[20]), "=r"((r)[21]), "=r"((r)[22]), "=r"((r)[23]), \
          "=r"((r)[24]), "=r"((r)[25]), "=r"((r)[26]), "=r"((r)[27]), \
          "=r"((r)[28]), "=r"((r)[29]), "=r"((r)[30]), "=r"((r)[31]) \
        : "r"(tmem))
#define TCGEN05_ST_32X32B_X32(tmem, r) \
    asm volatile("tcgen05.st.sync.aligned.32x32b.x32.b32 [%0], " \
        "{%1, %2, %3, %4, %5, %6, %7, %8, %9, %10, %11, %12, %13, %14, %15, %16, " \
        "%17, %18, %19, %20, %21, %22, %23, %24, %25, %26, %27, %28, %29, %30, %31, %32};" \
        :: "r"(tmem), \
           "r"((r)[0]),  "r"((r)[1]),  "r"((r)[2]),  "r"((r)[3]),  \
           "r"((r)[4]),  "r"((r)[5]),  "r"((r)[6]),  "r"((r)[7]),  \
           "r"((r)[8]),  "r"((r)[9]),  "r"((r)[10]), "r"((r)[11]), \
           "r"((r)[12]), "r"((r)[13]), "r"((r)[14]), "r"((r)[15]), \
           "r"((r)[16]), "r"((r)[17]), "r"((r)[18]), "r"((r)[19]), \
           "r"((r)[20]), "r"((r)[21]), "r"((r)[22]), "r"((r)[23]), \
           "r"((r)[24]), "r"((r)[25]), "r"((r)[26]), "r"((r)[27]), \
           "r"((r)[28]), "r"((r)[29]), "r"((r)[30]), "r"((r)[31]) \
        : "memory")
#define CP_ASYNC16(smem_u32, gptr) \
    asm volatile("cp.async.cg.shared.global [%0], [%1], 16;" \
        :: "r"((uint32_t)(smem_u32)), "l"(gptr) : "memory")
#define CP_COMMIT() asm volatile("cp.async.commit_group;" ::: "memory")
#define CP_WAIT(n)  asm volatile("cp.async.wait_group %0;" :: "n"(n) : "memory")
// K-major SW128 desc: layout=2, ver=1, SBO=64, LBO=1
#define SMEM_DESC_BASE_SW128 \
    ((uint64_t(2) << 61) | (uint64_t(1) << 46) | (uint64_t(64) << 32) | (uint64_t(1) << 16))
#define MAKE_SMEM_DESC(addr) (SMEM_DESC_BASE_SW128 | ((uint64_t)((addr) >> 4) & 0x3FFF))
// MN-major SW128 desc (TransB operand): layout=2, ver=1, SBO=8, LBO=64
#define SMEM_DESC_BASE_SW128_MN \
    ((uint64_t(2) << 61) | (uint64_t(1) << 46) | (uint64_t(8) << 32) | (uint64_t(64) << 16))
#define MAKE_SMEM_DESC_MN(addr) (SMEM_DESC_BASE_SW128_MN | ((uint64_t)((addr) >> 4) & 0x3FFF))
#define SW128(off) ((off) ^ (((off) >> 3) & 0x70))

#if HAS_TCGEN05
__device__ __forceinline__ void mma_f16_ss(uint32_t d_tmem, uint64_t a_desc,
                                           uint64_t b_desc, uint32_t idesc,
                                           bool accum) {
    uint32_t en = accum ? 1u : 0u;
    asm volatile(
        "{\n\t.reg .pred p;\n\tsetp.ne.u32 p, %5, 0;\n\t"
        "tcgen05.mma.cta_group::1.kind::f16 [%0], %1, %2, %3, {%4, %4, %4, %4}, p;\n\t}"
        :: "r"(d_tmem), "l"(a_desc), "l"(b_desc), "r"(idesc), "r"(0u), "r"(en)
        : "memory");
}
// TS-mode (A in TMEM)
__device__ __forceinline__ void mma_f16_ts(uint32_t d_tmem, uint32_t a_tmem,
                                           uint64_t b_desc, uint32_t idesc,
                                           bool accum) {
    uint32_t en = accum ? 1u : 0u;
    asm volatile(
        "{\n\t.reg .pred p;\n\tsetp.ne.u32 p, %5, 0;\n\t"
        "tcgen05.mma.cta_group::1.kind::f16 [%0], [%1], %2, %3, {%4, %4, %4, %4}, p;\n\t}"
        :: "r"(d_tmem), "r"(a_tmem), "l"(b_desc), "r"(idesc), "r"(0u), "r"(en)
        : "memory");
}
#endif

// idescs: dtype F32, a/b BF16, M=128
#define SIM_IDESC  ((1u << 4) | (1u << 7) | (1u << 10) | ((128u / 8u) << 17) | ((128u / 16u) << 24))
#define GEMM_IDESC ((1u << 4) | (1u << 7) | (1u << 10) | ((256u / 8u) << 17) | ((128u / 16u) << 24))
// colsum MMA: N=64, TransB (bit 16)
#define CS_IDESC   ((1u << 4) | (1u << 7) | (1u << 10) | ((64u / 8u) << 17) | ((128u / 16u) << 24) | (1u << 16))

#if HAS_TCGEN05
// 16 chained K=16 MMAs, K=256, 128x256-bf16 SW128 tiles
__device__ __forceinline__ void issue_tile_mma(uint32_t d_tmem, uint32_t a_smem,
                                               uint32_t b_smem, uint32_t mbar) {
    uint64_t a_base = MAKE_SMEM_DESC(a_smem);
    uint64_t b_base = MAKE_SMEM_DESC(b_smem);
    if (elect_one_pred()) {
        #pragma unroll
        for (int s = 0; s < 16; s++) {
            uint64_t off = (uint64_t)((s >> 2) * 1024 + (s & 3) * 2);
            mma_f16_ss(d_tmem, a_base + off, b_base + off, SIM_IDESC, s > 0);
        }
        TCGEN05_COMMIT(mbar);
    }
}
__device__ __forceinline__ void g1_issue(uint32_t d_tmem, uint32_t a_smem,
                                         uint32_t b_smem, uint32_t mbar,
                                         bool first_chunk) {
    uint64_t a_base = MAKE_SMEM_DESC(a_smem);
    uint64_t b_base = MAKE_SMEM_DESC(b_smem);
    if (elect_one_pred()) {
        #pragma unroll
        for (int s = 0; s < 8; s++) {
            uint64_t offA = (uint64_t)((s >> 2) * 1024 + (s & 3) * 2);
            uint64_t offB = (uint64_t)((s >> 2) * 2048 + (s & 3) * 2);
            mma_f16_ss(d_tmem, a_base + offA, b_base + offB, GEMM_IDESC,
                       !(first_chunk && s == 0));
        }
        TCGEN05_COMMIT(mbar);
    }
}
__device__ __forceinline__ void g1_load_A(const float* __restrict__ X, int row0,
                                          int k0, char* smem, uint32_t A_OFF,
                                          int tid) {
    #pragma unroll
    for (int i = 0; i < 8; i++) {
        int u = tid + i * 256;
        int r = u >> 4, q = u & 15;
        const float* src = X + (size_t)(row0 + r) * DIM + k0 + q * 8;
        float4 v0 = *(const float4*)src;
        float4 v1 = *(const float4*)(src + 4);
        __nv_bfloat162 h2[4];
        h2[0] = __floats2bfloat162_rn(v0.x, v0.y);
        h2[1] = __floats2bfloat162_rn(v0.z, v0.w);
        h2[2] = __floats2bfloat162_rn(v1.x, v1.y);
        h2[3] = __floats2bfloat162_rn(v1.z, v1.w);
        uint32_t byte_off = (uint32_t)((r >> 3) + ((q >> 3) << 4)) * 1024u
                          + (uint32_t)(r & 7) * 128u + (uint32_t)(q & 7) * 16u;
        *(uint4*)(smem + A_OFF + SW128(byte_off)) = *(uint4*)h2;
    }
}
__device__ __forceinline__ void g1_load_B(const __nv_bfloat16* __restrict__ Wt,
                                          int k0, uint32_t smem_base,
                                          uint32_t B_OFF, int tid) {
    #pragma unroll
    for (int i = 0; i < 16; i++) {
        int u = tid + i * 256;
        int r = u >> 4, q = u & 15;
        uint32_t byte_off = (uint32_t)((r >> 3) + ((q >> 3) << 5)) * 1024u
                          + (uint32_t)(r & 7) * 128u + (uint32_t)(q & 7) * 16u;
        CP_ASYNC16(smem_base + B_OFF + SW128(byte_off),
                   Wt + (size_t)r * DIM + k0 + q * 8);
    }
}
#endif

// ---------------------------------------------------------------------------
// K0: Wt transpose + zero cpart slot 31 lower half (rows <4096 never written)
// ---------------------------------------------------------------------------
__global__ void __launch_bounds__(256) k_prep(const float* __restrict__ W,
                                              __nv_bfloat16* __restrict__ Wt,
                                              float* __restrict__ cpart)
{
    __shared__ float S[64][68];
    const int k0 = blockIdx.x * 64, n0 = blockIdx.y * 64;
    const int tid = threadIdx.x;

    if (blockIdx.y == 0 && blockIdx.x < 16)
        cpart[(size_t)31 * NROWS + blockIdx.x * 256 + tid] = 0.f;

    #pragma unroll
    for (int i = 0; i < 4; i++) {
        int t = tid + i * 256;
        int r = t >> 4, c4 = t & 15;
        float4 v = *(const float4*)&W[(size_t)(k0 + r) * PD + n0 + c4 * 4];
        S[r][c4 * 4 + 0] = v.x; S[r][c4 * 4 + 1] = v.y;
        S[r][c4 * 4 + 2] = v.z; S[r][c4 * 4 + 3] = v.w;
    }
    __syncthreads();
    #pragma unroll
    for (int i = 0; i < 2; i++) {
        int u = tid + i * 256;
        int n = u >> 3, ku = u & 7;
        __nv_bfloat162 h2[4];
        #pragma unroll
        for (int m = 0; m < 4; m++)
            h2[m] = __floats2bfloat162_rn(S[ku * 8 + 2 * m][n], S[ku * 8 + 2 * m + 1][n]);
        *(uint4*)&Wt[(size_t)(n0 + n) * DIM + k0 + ku * 8] = *(uint4*)h2;
    }
}

// ---------------------------------------------------------------------------
// K1: tcgen05 GEMM1 + bias + fused L2-normalize -> bf16. (unchanged)
// ---------------------------------------------------------------------------
__global__ void __launch_bounds__(256, 1) k_gemm1_tc(
    const float* __restrict__ X, const __nv_bfloat16* __restrict__ Wt,
    const float* __restrict__ b, __nv_bfloat16* __restrict__ Nh)
{
    extern __shared__ __align__(16) char smem[];
    __shared__ float s_red[128][2];
    __shared__ float s_bias[256];

    const int tid = threadIdx.x;
    const int row0 = blockIdx.x * 128;
    s_bias[tid] = b[tid];

#if HAS_TCGEN05
    const uint32_t smem_base = smem_to_u32(smem);
    const uint32_t aoff = ((smem_base + 1024 + 1023) & ~1023u) - smem_base;
    const uint32_t A_OFF0 = aoff;
    const uint32_t A_OFF1 = aoff + 32768;
    const uint32_t B_OFF0 = aoff + 65536;
    const uint32_t B_OFF1 = aoff + 131072;
    const uint32_t TPTR = 0, MB0 = 16, MB1 = 24;

    if (tid < 32) {
        TCGEN05_ALLOC(smem_base + TPTR, 256);
        TCGEN05_RELINQUISH();
    }
    if (tid == 0) { MBARRIER_INIT(smem_base + MB0, 1); MBARRIER_INIT(smem_base + MB1, 1); }
    __syncthreads();
    uint32_t tmem;
    asm volatile("ld.shared.b32 %0, [%1];" : "=r"(tmem) : "r"(smem_base + TPTR));

    g1_load_B(Wt, 0, smem_base, B_OFF0, tid);
    CP_COMMIT();
    g1_load_A(X, row0, 0, smem, A_OFF0, tid);
    CP_WAIT(0);
    __syncthreads();
    FENCE_PROXY_ASYNC();

    int ph0 = 0, ph1 = 0;
    for (int c = 0; c < 16; c++) {
        const int buf = c & 1;
        if (tid < 32)
            g1_issue(tmem, smem_base + (buf ? A_OFF1 : A_OFF0),
                     smem_base + (buf ? B_OFF1 : B_OFF0),
                     smem_base + (buf ? MB1 : MB0), c == 0);
        if (c + 1 < 16) {
            if (c >= 1) {
                if (buf) { MBARRIER_WAIT_PARITY(smem_base + MB0, ph0); ph0 ^= 1; }
                else     { MBARRIER_WAIT_PARITY(smem_base + MB1, ph1); ph1 ^= 1; }
            }
            g1_load_B(Wt, (c + 1) * 128, smem_base, buf ? B_OFF0 : B_OFF1, tid);
            CP_COMMIT();
            g1_load_A(X, row0, (c + 1) * 128, smem, buf ? A_OFF0 : A_OFF1, tid);
            CP_WAIT(0);
            __syncthreads();
            FENCE_PROXY_ASYNC();
        }
    }
    MBARRIER_WAIT_PARITY(smem_base + MB1, ph1);
    TCGEN05_FENCE_AFTER();

    const int w = tid >> 5, lane = tid & 31;
    const int row = (w & 3) * 32 + lane;
    const int half = w >> 2;
    const uint32_t tbase = tmem + half * 128;

    float sumsq = 0.f;
    #pragma unroll
    for (int c8 = 0; c8 < 2; c8++) {
        uint32_t r0[32], r1[32];
        TCGEN05_LD_32X32B_X32(r0, tbase + c8 * 64);
        TCGEN05_LD_32X32B_X32(r1, tbase + c8 * 64 + 32);
        TCGEN05_WAIT_LD();
        #pragma unroll
        for (int j = 0; j < 32; j++) {
            float v0 = __uint_as_float(r0[j]) + s_bias[half * 128 + c8 * 64 + j];
            float v1 = __uint_as_float(r1[j]) + s_bias[half * 128 + c8 * 64 + 32 + j];
            sumsq += v0 * v0 + v1 * v1;
        }
    }
    s_red[row][half] = sumsq;
    __syncthreads();
    float inv = 1.0f / fmaxf(sqrtf(s_red[row][0] + s_red[row][1]), 1e-12f);

    const size_t gbase = (size_t)(row0 + row) * PD + half * 128;
    #pragma unroll
    for (int c8 = 0; c8 < 2; c8++) {
        uint32_t r0[32], r1[32];
        TCGEN05_LD_32X32B_X32(r0, tbase + c8 * 64);
        TCGEN05_LD_32X32B_X32(r1, tbase + c8 * 64 + 32);
        TCGEN05_WAIT_LD();
        float v[64];
        #pragma unroll
        for (int j = 0; j < 32; j++) {
            v[j]      = (__uint_as_float(r0[j]) + s_bias[half * 128 + c8 * 64 + j]) * inv;
            v[32 + j] = (__uint_as_float(r1[j]) + s_bias[half * 128 + c8 * 64 + 32 + j]) * inv;
        }
        __nv_bfloat162 hh[32];
        #pragma unroll
        for (int j2 = 0; j2 < 32; j2++)
            hh[j2] = __floats2bfloat162_rn(v[2 * j2], v[2 * j2 + 1]);
        #pragma unroll
        for (int q = 0; q < 8; q++)
            *(uint4*)&Nh[gbase + c8 * 64 + q * 8] = ((uint4*)hh)[q];
    }
    TCGEN05_FENCE_BEFORE();

    __syncthreads();
    if (tid == 0) { MBARRIER_INVAL(smem_base + MB0); MBARRIER_INVAL(smem_base + MB1); }
    __syncthreads();
    if (tid < 32) TCGEN05_DEALLOC(tmem, 256);
#else
    const int row = row0 + (tid & 127);
    if (tid < 128) {
        float sumsq = 0.f;
        for (int n = 0; n < PD; n++) {
            float s = 0.f;
            for (int k = 0; k < DIM; k++)
                s += X[(size_t)row * DIM + k] * __bfloat162float(Wt[(size_t)n * DIM + k]);
            s += s_bias[n];
            sumsq += s * s;
        }
        float inv = 1.0f / fmaxf(sqrtf(sumsq), 1e-12f);
        for (int n = 0; n < PD; n++) {
            float s = 0.f;
            for (int k = 0; k < DIM; k++)
                s += X[(size_t)row * DIM + k] * __bfloat162float(Wt[(size_t)n * DIM + k]);
            Nh[(size_t)row * PD + n] = __float2bfloat16((s + s_bias[n]) * inv);
        }
    }
#endif
}

// ---------------------------------------------------------------------------
// K4: SYMMETRIC pipelined sim. Grid (64 bi, 2 h), 256 thr. (unchanged from
// R15 except dead-code removal)
// ---------------------------------------------------------------------------
__global__ void __launch_bounds__(256, 1) k_sim_sym(
    const __nv_bfloat16* __restrict__ Nh, float* __restrict__ part,
    float* __restrict__ cpart, float* __restrict__ pos)
{
    extern __shared__ __align__(16) char smem[];
    const int tid = threadIdx.x;
    const int bi = blockIdx.x, h = blockIdx.y;
    const int ro = bi * 128;

#if HAS_TCGEN05
    const uint32_t smem_base = smem_to_u32(smem);
    const uint32_t aoff = ((smem_base + 1024 + 1023) & ~1023u) - smem_base;
    const uint32_t A_OFF  = aoff;
    const uint32_t B_OFF0 = aoff + 65536;
    const uint32_t B_OFF1 = aoff + 131072;
    const uint32_t E_OFF  = aoff + 196608;   // 32 KB: 2 panels x 16 KB
    const uint32_t TPTR = 0, MBAR0 = 16, MBAR1 = 24, MBAR2 = 32, CS_OFF = 64;
    float* csf = (float*)(smem + CS_OFF);

    const int t0 = h ? 16 : 0;
    const int Tend = h ? ((bi < 32) ? 32 : 31) : 15;
    const int tcs0 = h ? 16 : 1;

    if (tid < 32) { TCGEN05_ALLOC(smem_base + TPTR, 512); TCGEN05_RELINQUISH(); }
    if (tid == 0) {
        MBARRIER_INIT(smem_base + MBAR0, 1);
        MBARRIER_INIT(smem_base + MBAR1, 1);
        MBARRIER_INIT(smem_base + MBAR2, 1);
    }
    __syncthreads();
    uint32_t tmem;
    asm volatile("ld.shared.b32 %0, [%1];" : "=r"(tmem) : "r"(smem_base + TPTR));
    const uint32_t D0 = tmem, D1 = tmem + 128, D2 = tmem + 256, AONES = tmem + 384;

    if (tid < 128) {
        uint32_t ones[32];
        #pragma unroll
        for (int k2 = 0; k2 < 32; k2++) ones[k2] = 0x3F803F80u;
        uint32_t woff = ((uint32_t)(tid >> 5)) << 21;
        TCGEN05_ST_32X32B_X32(AONES + woff, ones);
        TCGEN05_ST_32X32B_X32(AONES + woff + 32, ones);
        TCGEN05_WAIT_ST();
    }
    TCGEN05_FENCE_BEFORE();

    uint32_t dstA[16], dst0[16], dst1[16], goff[16];
    #pragma unroll
    for (int it = 0; it < 16; it++) {
        int idx = tid + it * 256;
        int r = idx >> 5, q = idx & 31;
        uint32_t byte_off = (uint32_t)((r >> 3) + ((q >> 3) << 4)) * 1024u
                          + (uint32_t)(r & 7) * 128u + (uint32_t)(q & 7) * 16u;
        uint32_t sw = SW128(byte_off);
        dstA[it] = smem_base + A_OFF + sw;
        dst0[it] = smem_base + B_OFF0 + sw;
        dst1[it] = smem_base + B_OFF1 + sw;
        goff[it] = (uint32_t)(r * PD + q * 8);
    }

    const int w = tid >> 5, lane = tid & 31;
    const int row = (w & 3) * 32 + lane;
    const int chalf = w >> 2;
    const int gi = ro + row;
    uint32_t eaddr[8];
    #pragma unroll
    for (int u = 0; u < 8; u++) {
        uint32_t byte_off = (uint32_t)(row >> 3) * 1024u + (uint32_t)(row & 7) * 128u
                          + (uint32_t)u * 16u;
        eaddr[u] = smem_base + E_OFF + (uint32_t)chalf * 16384u + SW128(byte_off);
    }

    {
        const __nv_bfloat16* Arows = Nh + (size_t)ro * PD;
        const __nv_bfloat16* B0r = Nh + (size_t)(((bi + t0) & 63) * 128) * PD;
        const __nv_bfloat16* B1r = Nh + (size_t)(((bi + t0 + 1) & 63) * 128) * PD;
        #pragma unroll
        for (int it = 0; it < 16; it++) {
            CP_ASYNC16(dstA[it], Arows + goff[it]);
            CP_ASYNC16(dst0[it], B0r + goff[it]);
        }
        CP_COMMIT();
        #pragma unroll
        for (int it = 0; it < 16; it++)
            CP_ASYNC16(dst1[it], B1r + goff[it]);
        CP_COMMIT();
    }
    CP_WAIT(1);
    __syncthreads();
    FENCE_PROXY_ASYNC();

    if (tid < 32) issue_tile_mma(D0, smem_base + A_OFF, smem_base + B_OFF0,
                                 smem_base + MBAR0);

    int ph0 = 0, ph1 = 0, ph2 = 0;
    float acc0 = 0.f, acc1 = 0.f, acc2 = 0.f, acc3 = 0.f;
    float posval = 0.f;
    const uint64_t e_desc0 = MAKE_SMEM_DESC_MN(smem_base + E_OFF);
    const uint64_t e_desc1 = MAKE_SMEM_DESC_MN(smem_base + E_OFF + 16384);

    for (int t = t0; t <= Tend; t++) {
        const int buf = t & 1;
        if (buf) { MBARRIER_WAIT_PARITY(smem_base + MBAR1, ph1); ph1 ^= 1; }
        else     { MBARRIER_WAIT_PARITY(smem_base + MBAR0, ph0); ph0 ^= 1; }
        if (t + 2 <= Tend) {
            const __nv_bfloat16* Br = Nh + (size_t)(((bi + t + 2) & 63) * 128) * PD;
            #pragma unroll
            for (int it = 0; it < 16; it++)
                CP_ASYNC16(buf ? dst1[it] : dst0[it], Br + goff[it]);
        }
        CP_COMMIT();
        CP_WAIT(1);
        __syncthreads();
        FENCE_PROXY_ASYNC();
        TCGEN05_FENCE_AFTER();
        if (t + 1 <= Tend && tid < 32)
            issue_tile_mma(buf ? D0 : D1, smem_base + A_OFF,
                           smem_base + (buf ? B_OFF0 : B_OFF1),
                           smem_base + (buf ? MBAR0 : MBAR1));
        const bool havep = (t - 1 >= tcs0);
        if (havep) {
            MBARRIER_WAIT_PARITY(smem_base + MBAR2, ph2); ph2 ^= 1;
            TCGEN05_FENCE_AFTER();
            if (w < 4) {
                uint32_t rr[32];
                TCGEN05_LD_32X32B_X32(rr, D2 + w * 32);
                TCGEN05_WAIT_LD();
                if (lane == 0) {
                    #pragma unroll
                    for (int k2 = 0; k2 < 32; k2++)
                        csf[w * 32 + k2] = __uint_as_float(rr[k2]);
                }
            }
        }
        const uint32_t dt = (buf ? D1 : D0) + chalf * 64;
        uint32_t r0[32], r1[32];
        TCGEN05_LD_32X32B_X32(r0, dt);
        TCGEN05_LD_32X32B_X32(r1, dt + 32);
        TCGEN05_WAIT_LD();

        if (t == 0) {
            const int cb = chalf * 64;
            #pragma unroll
            for (int j = 0; j < 32; j++) {
                float e0 = exp2f(L2E10 * __uint_as_float(r0[j]));
                float e1 = exp2f(L2E10 * __uint_as_float(r1[j]));
                acc0 += (cb + j == row) ? 0.0f : e0;
                acc1 += (cb + 32 + j == row) ? 0.0f : e1;
            }
        } else if (t == 32) {
            const int cb = chalf * 64;
            #pragma unroll
            for (int u = 0; u < 4; u++) {
                __nv_bfloat162 hp[4];
                #pragma unroll
                for (int m = 0; m < 4; m++) {
                    int j = u * 8 + 2 * m;
                    float va = __uint_as_float(r0[j]);
                    float vb = __uint_as_float(r0[j + 1]);
                    if (cb + j == row) posval = va;
                    if (cb + j + 1 == row) posval = vb;
                    float ea = exp2f(L2E10 * va), eb = exp2f(L2E10 * vb);
                    acc0 += ea; acc1 += eb;
                    hp[m] = __floats2bfloat162_rn(ea, eb);
                }
                *(uint4*)((char*)smem + (eaddr[u] - smem_base)) = *(uint4*)hp;
            }
            #pragma unroll
            for (int u = 0; u < 4; u++) {
                __nv_bfloat162 hp[4];
                #pragma unroll
                for (int m = 0; m < 4; m++) {
                    int j = u * 8 + 2 * m;
                    float va = __uint_as_float(r1[j]);
                    float vb = __uint_as_float(r1[j + 1]);
                    if (cb + 32 + j == row) posval = va;
                    if (cb + 32 + j + 1 == row) posval = vb;
                    float ea = exp2f(L2E10 * va), eb = exp2f(L2E10 * vb);
                    acc2 += ea; acc3 += eb;
                    hp[m] = __floats2bfloat162_rn(ea, eb);
                }
                *(uint4*)((char*)smem + (eaddr[4 + u] - smem_base)) = *(uint4*)hp;
            }
        } else {
            #pragma unroll
            for (int u = 0; u < 4; u++) {
                __nv_bfloat162 hp[4];
                #pragma unroll
                for (int m = 0; m < 4; m++) {
                    int j = u * 8 + 2 * m;
                    float ea = exp2f(L2E10 * __uint_as_float(r0[j]));
                    float eb = exp2f(L2E10 * __uint_as_float(r0[j + 1]));
                    acc0 += ea; acc1 += eb;
                    hp[m] = __floats2bfloat162_rn(ea, eb);
                }
                *(uint4*)((char*)smem + (eaddr[u] - smem_base)) = *(uint4*)hp;
            }
            #pragma unroll
            for (int u = 0; u < 4; u++) {
                __nv_bfloat162 hp[4];
                #pragma unroll
                for (int m = 0; m < 4; m++) {
                    int j = u * 8 + 2 * m;
                    float ea = exp2f(L2E10 * __uint_as_float(r1[j]));
                    float eb = exp2f(L2E10 * __uint_as_float(r1[j + 1]));
                    acc2 += ea; acc3 += eb;
                    hp[m] = __floats2bfloat162_rn(ea, eb);
                }
                *(uint4*)((char*)smem + (eaddr[4 + u] - smem_base)) = *(uint4*)hp;
            }
        }
        TCGEN05_FENCE_BEFORE();
        __syncthreads();
        FENCE_PROXY_ASYNC();
        if (havep && tid < 128) {
            int jprev = (bi + (t - 1)) & 63;
            cpart[(size_t)(t - 2) * NROWS + jprev * 128 + tid] = csf[tid];
        }
        if (t >= tcs0 && tid < 32 && elect_one_pred()) {
            #pragma unroll
            for (int s = 0; s < 8; s++)
                mma_f16_ts(D2, AONES + s * 8, e_desc0 + (uint64_t)s * 128, CS_IDESC, s > 0);
            #pragma unroll
            for (int s = 0; s < 8; s++)
                mma_f16_ts(D2 + 64, AONES + s * 8, e_desc1 + (uint64_t)s * 128, CS_IDESC, s > 0);
            TCGEN05_COMMIT(smem_base + MBAR2);
        }
    }

    MBARRIER_WAIT_PARITY(smem_base + MBAR2, ph2);
    TCGEN05_FENCE_AFTER();
    if (w < 4) {
        uint32_t rr[32];
        TCGEN05_LD_32X32B_X32(rr, D2 + w * 32);
        TCGEN05_WAIT_LD();
        if (lane == 0) {
            #pragma unroll
            for (int k2 = 0; k2 < 32; k2++) csf[w * 32 + k2] = __uint_as_float(rr[k2]);
        }
    }
    TCGEN05_FENCE_BEFORE();
    __syncthreads();
    if (tid < 128) {
        int jl = (bi + Tend) & 63;
        cpart[(size_t)(Tend - 1) * NROWS + jl * 128 + tid] = csf[tid];
    }

    {
        float* red = (float*)(smem + E_OFF);
        red[row * 2 + chalf] = (acc0 + acc1) + (acc2 + acc3);
        __syncthreads();
        if (tid < 128)
            part[(size_t)h * NROWS + ro + tid] = red[tid * 2] + red[tid * 2 + 1];
    }
    if (h == 1 && bi < 32 && (row >> 6) == chalf)
        pos[gi] = posval;

    __syncthreads();
    if (tid == 0) {
        MBARRIER_INVAL(smem_base + MBAR0);
        MBARRIER_INVAL(smem_base + MBAR1);
        MBARRIER_INVAL(smem_base + MBAR2);
    }
    __syncthreads();
    if (tid < 32) TCGEN05_DEALLOC(tmem, 512);
#else
    // SIMT fallback (compile-only; never executed on GB300)
    if (tid < 128) {
        const int gi2 = ro + tid;
        const int T0 = h ? 16 : 0;
        const int T1 = h ? ((bi < 32) ? 32 : 31) : 15;
        const __nv_bfloat16* arow = Nh + (size_t)gi2 * PD;
        float rowsum = 0.f, pv = 0.f;
        for (int t = T0; t <= T1; t++) {
            int j = (bi + t) & 63;
            for (int c = 0; c < 128; c++) {
                int gc = j * 128 + c;
                const __nv_bfloat16* brow = Nh + (size_t)gc * PD;
                float s = 0.f;
                for (int k = 0; k < PD; k++)
                    s += __bfloat162float(arow[k]) * __bfloat162float(brow[k]);
                float e = __expf(10.0f * s);
                if (t == 0 && gc == gi2) e = 0.f;
                if (t == 32 && gc == gi2 + HALF) pv = s;
                rowsum += e;
            }
            if (t >= 1) {
                int gc = j * 128 + tid;
                const __nv_bfloat16* brow = Nh + (size_t)gc * PD;
                float cs = 0.f;
                for (int r2 = 0; r2 < 128; r2++) {
                    const __nv_bfloat16* ar = Nh + (size_t)(ro + r2) * PD;
                    float s = 0.f;
                    for (int k = 0; k < PD; k++)
                        s += __bfloat162float(ar[k]) * __bfloat162float(brow[k]);
                    cs += __expf(10.0f * s);
                }
                cpart[(size_t)(t - 1) * NROWS + gc] = cs;
            }
        }
        part[(size_t)h * NROWS + gi2] = rowsum;
        if (h == 1 && bi < 32) pos[gi2] = pv;
    }
#endif
}

// ---------------------------------------------------------------------------
// K6: parallel loss, WIDE. Grid 256 x 256. Block b owns 32 rows; 8 threads
// per row each sum 4 cpart slots (+part terms on sub 0), width-8 shfl
// combine, one log per row. pos: 16/block. Last block (ticket 255) reduces
// 256 partials in fixed order.
// ---------------------------------------------------------------------------
__global__ void __launch_bounds__(256) k_loss(const float* __restrict__ part,
                                              const float* __restrict__ cpart,
                                              const float* __restrict__ pos,
                                              float* __restrict__ lred,
                                              float* __restrict__ ppart,
                                              unsigned int* __restrict__ ctr,
                                              float* __restrict__ out)
{
    __shared__ float sh[256];
    __shared__ bool is_last;
    const int b = blockIdx.x;
    const int tid = threadIdx.x;
    const int rl = tid >> 3;           // local row 0..31
    const int sub = tid & 7;           // slot group
    const int gi = b * 32 + rl;

    // each thread: 4 slots (slot 31 lower half is zero-filled -> unconditional)
    float s4 = 0.f;
    #pragma unroll
    for (int k = 0; k < 4; k++)
        s4 += cpart[(size_t)(sub * 4 + k) * NROWS + gi];
    if (sub == 0)
        s4 += part[gi] + part[NROWS + gi];
    // width-8 combine within warp (fixed order)
    #pragma unroll
    for (int o = 4; o > 0; o >>= 1)
        s4 += __shfl_down_sync(0xffffffffu, s4, o, 8);
    float lrow = (sub == 0) ? logf(s4) : 0.f;

    // pos: 16 entries per block
    float p = (tid < 16) ? pos[b * 16 + tid] : 0.f;

    sh[tid] = lrow;
    __syncthreads();
    #pragma unroll
    for (int o = 128; o > 0; o >>= 1) {
        if (tid < o) sh[tid] += sh[tid + o];
        __syncthreads();
    }
    float lsum = sh[0];
    __syncthreads();
    sh[tid] = p;
    __syncthreads();
    #pragma unroll
    for (int o = 128; o > 0; o >>= 1) {
        if (tid < o) sh[tid] += sh[tid + o];
        __syncthreads();
    }
    if (tid == 0) {
        lred[b]  = lsum;
        ppart[b] = sh[0];
        __threadfence();
        unsigned int old = atomicAdd(ctr, 1u);
        is_last = (old == 255u);
    }
    __syncthreads();

    if (is_last) {
        float lv = lred[tid];
        float pv = ppart[tid];
        sh[tid] = lv;
        __syncthreads();
        #pragma unroll
        for (int o = 128; o > 0; o >>= 1) {
            if (tid < o) sh[tid] += sh[tid + o];
            __syncthreads();
        }
        float L = sh[0];
        __syncthreads();
        sh[tid] = pv;
        __syncthreads();
        #pragma unroll
        for (int o = 128; o > 0; o >>= 1) {
            if (tid < o) sh[tid] += sh[tid + o];
            __syncthreads();
        }
        if (tid == 0) {
            out[0] = (L - 20.0f * sh[0]) / (float)NROWS;
            *ctr = 0u;
        }
    }
}

// ---------------------------------------------------------------------------
extern "C" void kernel_launch(void* const* d_in, const int* in_sizes, int n_in,
                              void* d_out, int out_size)
{
    const float* X = (const float*)d_in[0];  // [8192, 2048]
    const float* W = (const float*)d_in[1];  // [2048, 256]
    const float* b = (const float*)d_in[2];  // [256]
    float* out = (float*)d_out;

    __nv_bfloat16* nrh;  cudaGetSymbolAddress((void**)&nrh,   g_normh);
    __nv_bfloat16* wt;   cudaGetSymbolAddress((void**)&wt,    g_Wt);
    float* part;         cudaGetSymbolAddress((void**)&part,  g_part);
    float* cpart;        cudaGetSymbolAddress((void**)&cpart, g_cpart);
    float* pos;          cudaGetSymbolAddress((void**)&pos,   g_pos);
    float* lred;         cudaGetSymbolAddress((void**)&lred,  g_lred);
    float* ppart;        cudaGetSymbolAddress((void**)&ppart, g_ppart);
    unsigned int* ctr;   cudaGetSymbolAddress((void**)&ctr,   g_ctr);

    const int SIM_SMEM  = 1024 + 1024 + 3 * 65536 + 32768;  // 231424 B
    const int GEMM_SMEM = 2048 + 2 * 32768 + 2 * 65536;     // 198656 B
    cudaFuncSetAttribute(k_sim_sym,
                         cudaFuncAttributeMaxDynamicSharedMemorySize, SIM_SMEM);
    cudaFuncSetAttribute(k_gemm1_tc,
                         cudaFuncAttributeMaxDynamicSharedMemorySize, GEMM_SMEM);

    k_prep<<<dim3(32, 4), 256>>>(W, wt, cpart);
    k_gemm1_tc<<<64, 256, GEMM_SMEM>>>(X, wt, b, nrh);
    k_sim_sym<<<dim3(64, 2), 256, SIM_SMEM>>>(nrh, part, cpart, pos);
    k_loss<<<256, 256>>>(part, cpart, pos, lred, ppart, ctr, out);
}